// round 5
// baseline (speedup 1.0000x reference)
#include <cuda_runtime.h>
#include <cuda_bf16.h>
#include <stdint.h>

#define MAX_N 50000
#define MAX_E 800000
#define HD    256

// ---------------- scratch ----------------
__device__ int   g_deg[MAX_N];
__device__ int   g_rowptr[MAX_N + 1];
__device__ int   g_cursor[MAX_N];
__device__ int   g_esrc[MAX_E];
__device__ float g_dinv[MAX_N];
__device__ int   g_bsum[64];
__device__ int   g_boff[64];
__device__ float g_agg[(size_t)MAX_N * HD];
__device__ float g_h[(size_t)MAX_N * HD];
// pre-transposed + bf16-split weights, layout [n][k]
__device__ __nv_bfloat16 g_W1h[256 * 128];
__device__ __nv_bfloat16 g_W1l[256 * 128];
__device__ __nv_bfloat16 g_W2h[256 * 256];
__device__ __nv_bfloat16 g_W2l[256 * 256];

// ---------------- setup kernels ----------------
__global__ void zero_deg_kernel(int n) {
    int i = blockIdx.x * blockDim.x + threadIdx.x;
    if (i < n) g_deg[i] = 0;
}
// MLP=4 histogram over dst
__global__ void hist4_kernel(const int* __restrict__ ei, int e) {
    int i = (blockIdx.x * blockDim.x + threadIdx.x) * 4;
    if (i + 3 < e) {
        int4 d = *(const int4*)(ei + e + i);
        atomicAdd(&g_deg[d.x], 1);
        atomicAdd(&g_deg[d.y], 1);
        atomicAdd(&g_deg[d.z], 1);
        atomicAdd(&g_deg[d.w], 1);
    } else {
        for (int j = i; j < e; j++) atomicAdd(&g_deg[ei[e + j]], 1);
    }
}
__global__ void hist1_kernel(const int* __restrict__ ei, int e) {
    int i = blockIdx.x * blockDim.x + threadIdx.x;
    if (i < e) atomicAdd(&g_deg[ei[e + i]], 1);
}

// phase 1: per-block (1024) local inclusive scan of deg; also dinv
__global__ __launch_bounds__(1024)
void scan1_kernel(int n) {
    __shared__ int sh[1024];
    int tid = threadIdx.x;
    int i = blockIdx.x * 1024 + tid;
    int v = (i < n) ? g_deg[i] : 0;
    if (i < n) g_dinv[i] = rsqrtf((float)(v + 1));
    sh[tid] = v;
    __syncthreads();
    #pragma unroll
    for (int d = 1; d < 1024; d <<= 1) {
        int t = (tid >= d) ? sh[tid - d] : 0;
        __syncthreads();
        sh[tid] += t;
        __syncthreads();
    }
    if (i < n) g_rowptr[i] = sh[tid];      // local inclusive (temp)
    if (tid == 1023) g_bsum[blockIdx.x] = sh[1023];
}
// phase 2: exclusive scan of block sums (<=64 blocks)
__global__ void scan2_kernel(int nb) {
    __shared__ int sh[64];
    int tid = threadIdx.x;
    int v = (tid < nb) ? g_bsum[tid] : 0;
    sh[tid] = v;
    __syncthreads();
    #pragma unroll
    for (int d = 1; d < 64; d <<= 1) {
        int t = (tid >= d) ? sh[tid - d] : 0;
        __syncthreads();
        sh[tid] += t;
        __syncthreads();
    }
    if (tid < nb) g_boff[tid] = sh[tid] - v;
}
// phase 3: rowptr/cursor = block offset + local exclusive
__global__ void scan3_kernel(int n, int e) {
    int i = blockIdx.x * blockDim.x + threadIdx.x;
    if (i < n) {
        int r = g_boff[i >> 10] + g_rowptr[i] - g_deg[i];
        g_rowptr[i] = r;
        g_cursor[i] = r;
    }
    if (i == 0) g_rowptr[n] = e;
}

// MLP=4 CSR bucket fill
__global__ void fill4_kernel(const int* __restrict__ ei, int e) {
    int i = (blockIdx.x * blockDim.x + threadIdx.x) * 4;
    if (i + 3 < e) {
        int4 s = *(const int4*)(ei + i);
        int4 d = *(const int4*)(ei + e + i);
        int p0 = atomicAdd(&g_cursor[d.x], 1);
        int p1 = atomicAdd(&g_cursor[d.y], 1);
        int p2 = atomicAdd(&g_cursor[d.z], 1);
        int p3 = atomicAdd(&g_cursor[d.w], 1);
        g_esrc[p0] = s.x; g_esrc[p1] = s.y; g_esrc[p2] = s.z; g_esrc[p3] = s.w;
    } else {
        for (int j = i; j < e; j++) {
            int src = ei[j];
            int pos = atomicAdd(&g_cursor[ei[e + j]], 1);
            g_esrc[pos] = src;
        }
    }
}
__global__ void fill1_kernel(const int* __restrict__ ei, int e) {
    int i = blockIdx.x * blockDim.x + threadIdx.x;
    if (i < e) {
        int src = ei[i];
        int pos = atomicAdd(&g_cursor[ei[e + i]], 1);
        g_esrc[pos] = src;
    }
}

// transpose + bf16-split both weight matrices in one launch
__global__ void prep_w_kernel(const float* __restrict__ W1, const float* __restrict__ W2,
                              __nv_bfloat16* __restrict__ W1h, __nv_bfloat16* __restrict__ W1l,
                              __nv_bfloat16* __restrict__ W2h, __nv_bfloat16* __restrict__ W2l) {
    int i = blockIdx.x * blockDim.x + threadIdx.x;
    if (i < 256 * 128) {
        int n = i / 128, k = i % 128;
        float w = W1[k * 256 + n];
        __nv_bfloat16 h = __float2bfloat16_rn(w);
        W1h[i] = h;
        W1l[i] = __float2bfloat16_rn(w - __bfloat162float(h));
    }
    int j = i - 256 * 128;
    if (j >= 0 && j < 256 * 256) {
        int n = j / 256, k = j % 256;
        float w = W2[k * 256 + n];
        __nv_bfloat16 h = __float2bfloat16_rn(w);
        W2h[j] = h;
        W2l[j] = __float2bfloat16_rn(w - __bfloat162float(h));
    }
}

// ---------------- aggregation (warp-per-node gather, unroll-2) ----------------
template <int F>
__global__ void agg_kernel(const float* __restrict__ x, float* __restrict__ out, int n) {
    int warp = blockIdx.x * (blockDim.x >> 5) + (threadIdx.x >> 5);
    int lane = threadIdx.x & 31;
    if (warp >= n) return;
    constexpr int V = F / 128;
    const float4* __restrict__ x4 = (const float4*)x;
    float di = g_dinv[warp];
    float4 acc[V];
    #pragma unroll
    for (int v = 0; v < V; v++) {
        float4 t = x4[(size_t)warp * (F / 4) + v * 32 + lane];
        acc[v].x = di * t.x; acc[v].y = di * t.y;
        acc[v].z = di * t.z; acc[v].w = di * t.w;
    }
    int beg = g_rowptr[warp], end = g_rowptr[warp + 1];
    int e = beg;
    for (; e + 1 < end; e += 2) {
        int s0 = g_esrc[e], s1 = g_esrc[e + 1];
        float w0 = g_dinv[s0], w1 = g_dinv[s1];
        float4 t0[V], t1[V];
        #pragma unroll
        for (int v = 0; v < V; v++) {
            t0[v] = x4[(size_t)s0 * (F / 4) + v * 32 + lane];
            t1[v] = x4[(size_t)s1 * (F / 4) + v * 32 + lane];
        }
        #pragma unroll
        for (int v = 0; v < V; v++) {
            acc[v].x = fmaf(w0, t0[v].x, acc[v].x);
            acc[v].y = fmaf(w0, t0[v].y, acc[v].y);
            acc[v].z = fmaf(w0, t0[v].z, acc[v].z);
            acc[v].w = fmaf(w0, t0[v].w, acc[v].w);
            acc[v].x = fmaf(w1, t1[v].x, acc[v].x);
            acc[v].y = fmaf(w1, t1[v].y, acc[v].y);
            acc[v].z = fmaf(w1, t1[v].z, acc[v].z);
            acc[v].w = fmaf(w1, t1[v].w, acc[v].w);
        }
    }
    if (e < end) {
        int s = g_esrc[e];
        float w = g_dinv[s];
        #pragma unroll
        for (int v = 0; v < V; v++) {
            float4 t = x4[(size_t)s * (F / 4) + v * 32 + lane];
            acc[v].x = fmaf(w, t.x, acc[v].x);
            acc[v].y = fmaf(w, t.y, acc[v].y);
            acc[v].z = fmaf(w, t.z, acc[v].z);
            acc[v].w = fmaf(w, t.w, acc[v].w);
        }
    }
    float4* __restrict__ o4 = (float4*)out;
    #pragma unroll
    for (int v = 0; v < V; v++) {
        float4 r;
        r.x = di * acc[v].x; r.y = di * acc[v].y;
        r.z = di * acc[v].z; r.w = di * acc[v].w;
        o4[(size_t)warp * (F / 4) + v * 32 + lane] = r;
    }
}

// ---------------- tensor GEMM via mma.sync, double-buffered + reg prefetch ----
__device__ __forceinline__ void mma_bf16(float* c, const uint32_t* a, uint32_t b0, uint32_t b1) {
    asm volatile(
        "mma.sync.aligned.m16n8k16.row.col.f32.bf16.bf16.f32 "
        "{%0,%1,%2,%3}, {%4,%5,%6,%7}, {%8,%9}, {%0,%1,%2,%3};"
        : "+f"(c[0]), "+f"(c[1]), "+f"(c[2]), "+f"(c[3])
        : "r"(a[0]), "r"(a[1]), "r"(a[2]), "r"(a[3]), "r"(b0), "r"(b1));
}

#define KC 32
#define KS_STRIDE 40            // bf16 row stride; conflict-free frag pattern
#define ASZ (128 * KS_STRIDE)   // bf16 elems per array (5120)
#define GEMM_SMEM (2 * 4 * ASZ * 2)  // 2 buffers x 4 arrays x ASZ bf16 x 2B = 81920

template <int K>
__global__ __launch_bounds__(256, 1)
void gemm_mma(const float* __restrict__ A, const __nv_bfloat16* __restrict__ Wh,
              const __nv_bfloat16* __restrict__ Wl, const float* __restrict__ bias,
              float* __restrict__ C, int M) {
    extern __shared__ __nv_bfloat16 sm[];
    const int tid = threadIdx.x;
    const int wid = tid >> 5;
    const int lane = tid & 31;
    const int row0 = blockIdx.x * 128;
    const int colbase = blockIdx.y * 128;
    const int m_off = (wid & 3) * 32;
    const int n_off = (wid >> 2) * 64;
    constexpr int CHUNKS = K / KC;

    float acc[2][8][4];
    #pragma unroll
    for (int mt = 0; mt < 2; mt++)
        #pragma unroll
        for (int nt = 0; nt < 8; nt++)
            #pragma unroll
            for (int q = 0; q < 4; q++) acc[mt][nt][q] = 0.f;

    float4 va[4];
    uint2 vbh[4], vbl[4];
    const int st_r = tid >> 3;           // row/col 0..127 (i>>3 with it folded below)
    const int st_q = (tid & 7) * 4;      // k offset 0..28

    // prefetch chunk c into regs
    auto loadg = [&](int c) {
        int k0 = c * KC;
        #pragma unroll
        for (int it = 0; it < 4; it++) {
            int r = st_r + it * 32;
            va[it] = make_float4(0.f, 0.f, 0.f, 0.f);
            if (row0 + r < M)
                va[it] = *(const float4*)(A + (size_t)(row0 + r) * K + k0 + st_q);
            vbh[it] = *(const uint2*)(Wh + (size_t)(colbase + r) * K + k0 + st_q);
            vbl[it] = *(const uint2*)(Wl + (size_t)(colbase + r) * K + k0 + st_q);
        }
    };
    // convert + store regs into buffer b
    auto stores = [&](int b) {
        __nv_bfloat16* Ah = sm + b * 4 * ASZ;
        __nv_bfloat16* Al = Ah + ASZ;
        __nv_bfloat16* Bh = Ah + 2 * ASZ;
        __nv_bfloat16* Bl = Ah + 3 * ASZ;
        #pragma unroll
        for (int it = 0; it < 4; it++) {
            int r = st_r + it * 32;
            float4 v = va[it];
            float hx = __bfloat162float(__float2bfloat16_rn(v.x));
            float hy = __bfloat162float(__float2bfloat16_rn(v.y));
            float hz = __bfloat162float(__float2bfloat16_rn(v.z));
            float hw = __bfloat162float(__float2bfloat16_rn(v.w));
            __nv_bfloat162* ph = (__nv_bfloat162*)(Ah + r * KS_STRIDE + st_q);
            __nv_bfloat162* pl = (__nv_bfloat162*)(Al + r * KS_STRIDE + st_q);
            ph[0] = __floats2bfloat162_rn(hx, hy);
            ph[1] = __floats2bfloat162_rn(hz, hw);
            pl[0] = __floats2bfloat162_rn(v.x - hx, v.y - hy);
            pl[1] = __floats2bfloat162_rn(v.z - hz, v.w - hw);
            *(uint2*)(Bh + r * KS_STRIDE + st_q) = vbh[it];
            *(uint2*)(Bl + r * KS_STRIDE + st_q) = vbl[it];
        }
    };
    auto compute = [&](int b) {
        const __nv_bfloat16* Ah = sm + b * 4 * ASZ;
        const __nv_bfloat16* Al = Ah + ASZ;
        const __nv_bfloat16* Bh = Ah + 2 * ASZ;
        const __nv_bfloat16* Bl = Ah + 3 * ASZ;
        #pragma unroll
        for (int ks = 0; ks < KC; ks += 16) {
            uint32_t ah[2][4], al[2][4];
            int cofs = ks + (lane & 3) * 2;
            #pragma unroll
            for (int mt = 0; mt < 2; mt++) {
                int r = m_off + mt * 16 + (lane >> 2);
                ah[mt][0] = *(const uint32_t*)(Ah + r * KS_STRIDE + cofs);
                ah[mt][1] = *(const uint32_t*)(Ah + (r + 8) * KS_STRIDE + cofs);
                ah[mt][2] = *(const uint32_t*)(Ah + r * KS_STRIDE + cofs + 8);
                ah[mt][3] = *(const uint32_t*)(Ah + (r + 8) * KS_STRIDE + cofs + 8);
                al[mt][0] = *(const uint32_t*)(Al + r * KS_STRIDE + cofs);
                al[mt][1] = *(const uint32_t*)(Al + (r + 8) * KS_STRIDE + cofs);
                al[mt][2] = *(const uint32_t*)(Al + r * KS_STRIDE + cofs + 8);
                al[mt][3] = *(const uint32_t*)(Al + (r + 8) * KS_STRIDE + cofs + 8);
            }
            #pragma unroll
            for (int nt = 0; nt < 8; nt++) {
                int cc = n_off + nt * 8 + (lane >> 2);
                uint32_t bh0 = *(const uint32_t*)(Bh + cc * KS_STRIDE + cofs);
                uint32_t bh1 = *(const uint32_t*)(Bh + cc * KS_STRIDE + cofs + 8);
                uint32_t bl0 = *(const uint32_t*)(Bl + cc * KS_STRIDE + cofs);
                uint32_t bl1 = *(const uint32_t*)(Bl + cc * KS_STRIDE + cofs + 8);
                #pragma unroll
                for (int mt = 0; mt < 2; mt++) {
                    mma_bf16(acc[mt][nt], ah[mt], bh0, bh1);
                    mma_bf16(acc[mt][nt], al[mt], bh0, bh1);
                    mma_bf16(acc[mt][nt], ah[mt], bl0, bl1);
                }
            }
        }
    };

    loadg(0);
    stores(0);
    __syncthreads();
    for (int c = 0; c < CHUNKS; c++) {
        if (c + 1 < CHUNKS) loadg(c + 1);     // in-flight during compute
        compute(c & 1);
        if (c + 1 < CHUNKS) stores((c + 1) & 1);
        __syncthreads();
    }

    // epilogue: bias + relu + store
    #pragma unroll
    for (int mt = 0; mt < 2; mt++) {
        int row = row0 + m_off + mt * 16 + (lane >> 2);
        #pragma unroll
        for (int nt = 0; nt < 8; nt++) {
            int col = colbase + n_off + nt * 8 + (lane & 3) * 2;
            float b0 = bias[col], b1 = bias[col + 1];
            if (row < M) {
                float2 o;
                o.x = acc[mt][nt][0] + b0; o.y = acc[mt][nt][1] + b1;
                o.x = o.x > 0.f ? o.x : 0.f;
                o.y = o.y > 0.f ? o.y : 0.f;
                *(float2*)(C + (size_t)row * 256 + col) = o;
            }
            if (row + 8 < M) {
                float2 o;
                o.x = acc[mt][nt][2] + b0; o.y = acc[mt][nt][3] + b1;
                o.x = o.x > 0.f ? o.x : 0.f;
                o.y = o.y > 0.f ? o.y : 0.f;
                *(float2*)(C + (size_t)(row + 8) * 256 + col) = o;
            }
        }
    }
}

// ---------------- pooling + heads ----------------
__device__ __forceinline__ int lower_bound_i(const int* __restrict__ a, int n, int key) {
    int lo = 0, hi = n;
    while (lo < hi) {
        int mid = (lo + hi) >> 1;
        if (a[mid] < key) lo = mid + 1; else hi = mid;
    }
    return lo;
}
__global__ __launch_bounds__(256)
void pool_heads_kernel(const float* __restrict__ h, const int* __restrict__ batch,
                       const float* __restrict__ Wmu, const float* __restrict__ bmu,
                       const float* __restrict__ Wlv, const float* __restrict__ blv,
                       float* __restrict__ out, int n, int g_total) {
    int g = blockIdx.x;
    __shared__ float hg[256];
    int lo = lower_bound_i(batch, n, g);
    int hi = lower_bound_i(batch, n, g + 1);
    int tid = threadIdx.x;
    float s = 0.f;
    for (int i = lo; i < hi; i++) s += h[(size_t)i * 256 + tid];
    float cnt = (float)(hi - lo);
    hg[tid] = s / fmaxf(cnt, 1.0f);
    __syncthreads();
    if (tid < 64) {
        float m = bmu[tid];
        #pragma unroll 8
        for (int k = 0; k < 256; k++) m = fmaf(hg[k], Wmu[k * 64 + tid], m);
        out[g * 64 + tid] = m;
    } else if (tid < 128) {
        int t = tid - 64;
        float m = blv[t];
        #pragma unroll 8
        for (int k = 0; k < 256; k++) m = fmaf(hg[k], Wlv[k * 64 + t], m);
        out[(size_t)g_total * 64 + g * 64 + t] = m;
    }
}

// ---------------- launch ----------------
extern "C" void kernel_launch(void* const* d_in, const int* in_sizes, int n_in,
                              void* d_out, int out_size) {
    const float* x     = (const float*)d_in[0];
    const int*   ei    = (const int*)d_in[1];
    const int*   batch = (const int*)d_in[2];
    int wi = (n_in >= 12) ? 4 : 3;
    const float* W1  = (const float*)d_in[wi + 0];
    const float* b1  = (const float*)d_in[wi + 1];
    const float* W2  = (const float*)d_in[wi + 2];
    const float* b2  = (const float*)d_in[wi + 3];
    const float* Wmu = (const float*)d_in[wi + 4];
    const float* bmu = (const float*)d_in[wi + 5];
    const float* Wlv = (const float*)d_in[wi + 6];
    const float* blv = (const float*)d_in[wi + 7];
    float* out = (float*)d_out;

    int n = in_sizes[0] / 128;
    int e = in_sizes[1] / 2;
    int g = out_size / 128;

    static float* p_agg = nullptr;
    static float* p_h = nullptr;
    static __nv_bfloat16* p_w1h = nullptr; static __nv_bfloat16* p_w1l = nullptr;
    static __nv_bfloat16* p_w2h = nullptr; static __nv_bfloat16* p_w2l = nullptr;
    if (!p_agg) {
        cudaGetSymbolAddress((void**)&p_agg, g_agg);
        cudaGetSymbolAddress((void**)&p_h, g_h);
        cudaGetSymbolAddress((void**)&p_w1h, g_W1h);
        cudaGetSymbolAddress((void**)&p_w1l, g_W1l);
        cudaGetSymbolAddress((void**)&p_w2h, g_W2h);
        cudaGetSymbolAddress((void**)&p_w2l, g_W2l);
        cudaFuncSetAttribute(gemm_mma<128>, cudaFuncAttributeMaxDynamicSharedMemorySize, GEMM_SMEM);
        cudaFuncSetAttribute(gemm_mma<256>, cudaFuncAttributeMaxDynamicSharedMemorySize, GEMM_SMEM);
    }

    int nb = (n + 1023) / 1024;   // scan blocks (<=49 for N=50K)

    zero_deg_kernel<<<(n + 255) / 256, 256>>>(n);
    if ((e & 3) == 0) hist4_kernel<<<(e / 4 + 255) / 256, 256>>>(ei, e);
    else              hist1_kernel<<<(e + 255) / 256, 256>>>(ei, e);
    scan1_kernel<<<nb, 1024>>>(n);
    scan2_kernel<<<1, 64>>>(nb);
    scan3_kernel<<<(n + 255) / 256, 256>>>(n, e);
    if ((e & 3) == 0) fill4_kernel<<<(e / 4 + 255) / 256, 256>>>(ei, e);
    else              fill1_kernel<<<(e + 255) / 256, 256>>>(ei, e);
    prep_w_kernel<<<(256 * 128 + 256 * 256 + 255) / 256, 256>>>(W1, W2, p_w1h, p_w1l, p_w2h, p_w2l);

    agg_kernel<128><<<(n + 7) / 8, 256>>>(x, p_agg, n);
    gemm_mma<128><<<dim3((n + 127) / 128, 2), 256, GEMM_SMEM>>>(p_agg, p_w1h, p_w1l, b1, p_h, n);
    agg_kernel<256><<<(n + 7) / 8, 256>>>(p_h, p_agg, n);
    gemm_mma<256><<<dim3((n + 127) / 128, 2), 256, GEMM_SMEM>>>(p_agg, p_w2h, p_w2l, b2, p_h, n);
    pool_heads_kernel<<<g, 256>>>(p_h, batch, Wmu, bmu, Wlv, blv, out, n, g);
}

// round 6
// speedup vs baseline: 1.4348x; 1.4348x over previous
#include <cuda_runtime.h>
#include <cuda_bf16.h>
#include <stdint.h>

#define MAX_N 50000
#define MAX_E 800000
#define HD    256

// ---------------- scratch ----------------
__device__ int   g_deg[MAX_N];
__device__ int   g_rowptr[MAX_N + 1];
__device__ int   g_cursor[MAX_N];
__device__ int   g_esrc[MAX_E];
__device__ float g_dinv[MAX_N];
__device__ int   g_bsum[64];
__device__ float g_agg[(size_t)MAX_N * HD];
__device__ float g_h[(size_t)MAX_N * HD];
// pre-transposed + bf16-split weights, layout [n][k]
__device__ __nv_bfloat16 g_W1h[256 * 128];
__device__ __nv_bfloat16 g_W1l[256 * 128];
__device__ __nv_bfloat16 g_W2h[256 * 256];
__device__ __nv_bfloat16 g_W2l[256 * 256];

// ---------------- fused setup: zero deg + transpose/split both weights ------
__global__ void setup_kernel(const float* __restrict__ W1, const float* __restrict__ W2,
                             __nv_bfloat16* __restrict__ W1h, __nv_bfloat16* __restrict__ W1l,
                             __nv_bfloat16* __restrict__ W2h, __nv_bfloat16* __restrict__ W2l,
                             int n) {
    int i = blockIdx.x * blockDim.x + threadIdx.x;
    if (i < n) g_deg[i] = 0;
    if (i < 256 * 128) {
        int nn = i >> 7, k = i & 127;
        float w = W1[k * 256 + nn];
        __nv_bfloat16 h = __float2bfloat16_rn(w);
        W1h[i] = h;
        W1l[i] = __float2bfloat16_rn(w - __bfloat162float(h));
    }
    if (i < 256 * 256) {
        int nn = i >> 8, k = i & 255;
        float w = W2[k * 256 + nn];
        __nv_bfloat16 h = __float2bfloat16_rn(w);
        W2h[i] = h;
        W2l[i] = __float2bfloat16_rn(w - __bfloat162float(h));
    }
}

// MLP=4 histogram over dst
__global__ void hist4_kernel(const int* __restrict__ ei, int e) {
    int i = (blockIdx.x * blockDim.x + threadIdx.x) * 4;
    if (i + 3 < e) {
        int4 d = *(const int4*)(ei + e + i);
        atomicAdd(&g_deg[d.x], 1);
        atomicAdd(&g_deg[d.y], 1);
        atomicAdd(&g_deg[d.z], 1);
        atomicAdd(&g_deg[d.w], 1);
    } else {
        for (int j = i; j < e; j++) atomicAdd(&g_deg[ei[e + j]], 1);
    }
}
__global__ void hist1_kernel(const int* __restrict__ ei, int e) {
    int i = blockIdx.x * blockDim.x + threadIdx.x;
    if (i < e) atomicAdd(&g_deg[ei[e + i]], 1);
}

// phase 1: per-block (1024) local inclusive scan of deg; also dinv
__global__ __launch_bounds__(1024)
void scan1_kernel(int n) {
    __shared__ int sh[1024];
    int tid = threadIdx.x;
    int i = blockIdx.x * 1024 + tid;
    int v = (i < n) ? g_deg[i] : 0;
    if (i < n) g_dinv[i] = rsqrtf((float)(v + 1));
    sh[tid] = v;
    __syncthreads();
    #pragma unroll
    for (int d = 1; d < 1024; d <<= 1) {
        int t = (tid >= d) ? sh[tid - d] : 0;
        __syncthreads();
        sh[tid] += t;
        __syncthreads();
    }
    if (i < n) g_rowptr[i] = sh[tid];      // local inclusive (temp)
    if (tid == 1023) g_bsum[blockIdx.x] = sh[1023];
}
// phase 2 (fused): rowptr/cursor = inline block-offset + local exclusive
__global__ void scan3_kernel(int n, int e) {
    int win = blockIdx.x >> 2;              // 1024-window index of this 256-block
    int off = 0;
    for (int j = 0; j < win; j++) off += g_bsum[j];   // <=48 L1-hit loads
    int i = blockIdx.x * blockDim.x + threadIdx.x;
    if (i < n) {
        int r = off + g_rowptr[i] - g_deg[i];
        g_rowptr[i] = r;
        g_cursor[i] = r;
    }
    if (i == 0) g_rowptr[n] = e;
}

// MLP=4 CSR bucket fill
__global__ void fill4_kernel(const int* __restrict__ ei, int e) {
    int i = (blockIdx.x * blockDim.x + threadIdx.x) * 4;
    if (i + 3 < e) {
        int4 s = *(const int4*)(ei + i);
        int4 d = *(const int4*)(ei + e + i);
        int p0 = atomicAdd(&g_cursor[d.x], 1);
        int p1 = atomicAdd(&g_cursor[d.y], 1);
        int p2 = atomicAdd(&g_cursor[d.z], 1);
        int p3 = atomicAdd(&g_cursor[d.w], 1);
        g_esrc[p0] = s.x; g_esrc[p1] = s.y; g_esrc[p2] = s.z; g_esrc[p3] = s.w;
    } else {
        for (int j = i; j < e; j++) {
            int src = ei[j];
            int pos = atomicAdd(&g_cursor[ei[e + j]], 1);
            g_esrc[pos] = src;
        }
    }
}
__global__ void fill1_kernel(const int* __restrict__ ei, int e) {
    int i = blockIdx.x * blockDim.x + threadIdx.x;
    if (i < e) {
        int src = ei[i];
        int pos = atomicAdd(&g_cursor[ei[e + i]], 1);
        g_esrc[pos] = src;
    }
}

// ---------------- aggregation (warp-per-node gather, unroll-2) ----------------
template <int F>
__global__ void agg_kernel(const float* __restrict__ x, float* __restrict__ out, int n) {
    int warp = blockIdx.x * (blockDim.x >> 5) + (threadIdx.x >> 5);
    int lane = threadIdx.x & 31;
    if (warp >= n) return;
    constexpr int V = F / 128;
    const float4* __restrict__ x4 = (const float4*)x;
    float di = g_dinv[warp];
    float4 acc[V];
    #pragma unroll
    for (int v = 0; v < V; v++) {
        float4 t = x4[(size_t)warp * (F / 4) + v * 32 + lane];
        acc[v].x = di * t.x; acc[v].y = di * t.y;
        acc[v].z = di * t.z; acc[v].w = di * t.w;
    }
    int beg = g_rowptr[warp], end = g_rowptr[warp + 1];
    int e = beg;
    for (; e + 1 < end; e += 2) {
        int s0 = g_esrc[e], s1 = g_esrc[e + 1];
        float w0 = g_dinv[s0], w1 = g_dinv[s1];
        float4 t0[V], t1[V];
        #pragma unroll
        for (int v = 0; v < V; v++) {
            t0[v] = x4[(size_t)s0 * (F / 4) + v * 32 + lane];
            t1[v] = x4[(size_t)s1 * (F / 4) + v * 32 + lane];
        }
        #pragma unroll
        for (int v = 0; v < V; v++) {
            acc[v].x = fmaf(w0, t0[v].x, acc[v].x);
            acc[v].y = fmaf(w0, t0[v].y, acc[v].y);
            acc[v].z = fmaf(w0, t0[v].z, acc[v].z);
            acc[v].w = fmaf(w0, t0[v].w, acc[v].w);
            acc[v].x = fmaf(w1, t1[v].x, acc[v].x);
            acc[v].y = fmaf(w1, t1[v].y, acc[v].y);
            acc[v].z = fmaf(w1, t1[v].z, acc[v].z);
            acc[v].w = fmaf(w1, t1[v].w, acc[v].w);
        }
    }
    if (e < end) {
        int s = g_esrc[e];
        float w = g_dinv[s];
        #pragma unroll
        for (int v = 0; v < V; v++) {
            float4 t = x4[(size_t)s * (F / 4) + v * 32 + lane];
            acc[v].x = fmaf(w, t.x, acc[v].x);
            acc[v].y = fmaf(w, t.y, acc[v].y);
            acc[v].z = fmaf(w, t.z, acc[v].z);
            acc[v].w = fmaf(w, t.w, acc[v].w);
        }
    }
    float4* __restrict__ o4 = (float4*)out;
    #pragma unroll
    for (int v = 0; v < V; v++) {
        float4 r;
        r.x = di * acc[v].x; r.y = di * acc[v].y;
        r.z = di * acc[v].z; r.w = di * acc[v].w;
        o4[(size_t)warp * (F / 4) + v * 32 + lane] = r;
    }
}

// ---------------- tensor GEMM via mma.sync (round-3 proven config) ----------
// C[M,256] = relu(A[M,K] @ W[K,256] + b), bf16 3-term split, fp32 accum.
__device__ __forceinline__ void mma_bf16(float* c, const uint32_t* a, uint32_t b0, uint32_t b1) {
    asm volatile(
        "mma.sync.aligned.m16n8k16.row.col.f32.bf16.bf16.f32 "
        "{%0,%1,%2,%3}, {%4,%5,%6,%7}, {%8,%9}, {%0,%1,%2,%3};"
        : "+f"(c[0]), "+f"(c[1]), "+f"(c[2]), "+f"(c[3])
        : "r"(a[0]), "r"(a[1]), "r"(a[2]), "r"(a[3]), "r"(b0), "r"(b1));
}

#define KC 32
#define KS_STRIDE 40   // bf16 row stride (20 words): conflict-free for frag pattern

template <int K>
__global__ __launch_bounds__(256, 2)
void gemm_mma(const float* __restrict__ A, const __nv_bfloat16* __restrict__ Wh,
              const __nv_bfloat16* __restrict__ Wl, const float* __restrict__ bias,
              float* __restrict__ C, int M) {
    __shared__ __nv_bfloat16 sAh[128 * KS_STRIDE];
    __shared__ __nv_bfloat16 sAl[128 * KS_STRIDE];
    __shared__ __nv_bfloat16 sBh[128 * KS_STRIDE];
    __shared__ __nv_bfloat16 sBl[128 * KS_STRIDE];

    const int tid = threadIdx.x;
    const int wid = tid >> 5;
    const int lane = tid & 31;
    const int row0 = blockIdx.x * 128;
    const int colbase = blockIdx.y * 128;
    const int m_off = (wid & 3) * 32;
    const int n_off = (wid >> 2) * 64;

    float acc[2][8][4];
    #pragma unroll
    for (int mt = 0; mt < 2; mt++)
        #pragma unroll
        for (int nt = 0; nt < 8; nt++)
            #pragma unroll
            for (int q = 0; q < 4; q++) acc[mt][nt][q] = 0.f;

    for (int k0 = 0; k0 < K; k0 += KC) {
        #pragma unroll
        for (int it = 0; it < 4; it++) {
            int i = tid + it * 256;
            int r = i >> 3;
            int q = (i & 7) * 4;
            float4 v = make_float4(0.f, 0.f, 0.f, 0.f);
            if (row0 + r < M)
                v = *(const float4*)(A + (size_t)(row0 + r) * K + k0 + q);
            float hx = __bfloat162float(__float2bfloat16_rn(v.x));
            float hy = __bfloat162float(__float2bfloat16_rn(v.y));
            float hz = __bfloat162float(__float2bfloat16_rn(v.z));
            float hw = __bfloat162float(__float2bfloat16_rn(v.w));
            __nv_bfloat162* ph = (__nv_bfloat162*)(sAh + r * KS_STRIDE + q);
            __nv_bfloat162* pl = (__nv_bfloat162*)(sAl + r * KS_STRIDE + q);
            ph[0] = __floats2bfloat162_rn(hx, hy);
            ph[1] = __floats2bfloat162_rn(hz, hw);
            pl[0] = __floats2bfloat162_rn(v.x - hx, v.y - hy);
            pl[1] = __floats2bfloat162_rn(v.z - hz, v.w - hw);
        }
        #pragma unroll
        for (int it = 0; it < 4; it++) {
            int i = tid + it * 256;
            int nn = i >> 3;
            int q = (i & 7) * 4;
            const uint2* gh = (const uint2*)(Wh + (size_t)(colbase + nn) * K + k0 + q);
            const uint2* gl = (const uint2*)(Wl + (size_t)(colbase + nn) * K + k0 + q);
            *(uint2*)(sBh + nn * KS_STRIDE + q) = *gh;
            *(uint2*)(sBl + nn * KS_STRIDE + q) = *gl;
        }
        __syncthreads();

        #pragma unroll
        for (int ks = 0; ks < KC; ks += 16) {
            uint32_t ah[2][4], al[2][4];
            #pragma unroll
            for (int mt = 0; mt < 2; mt++) {
                int r = m_off + mt * 16 + (lane >> 2);
                int cofs = ks + (lane & 3) * 2;
                ah[mt][0] = *(const uint32_t*)(sAh + r * KS_STRIDE + cofs);
                ah[mt][1] = *(const uint32_t*)(sAh + (r + 8) * KS_STRIDE + cofs);
                ah[mt][2] = *(const uint32_t*)(sAh + r * KS_STRIDE + cofs + 8);
                ah[mt][3] = *(const uint32_t*)(sAh + (r + 8) * KS_STRIDE + cofs + 8);
                al[mt][0] = *(const uint32_t*)(sAl + r * KS_STRIDE + cofs);
                al[mt][1] = *(const uint32_t*)(sAl + (r + 8) * KS_STRIDE + cofs);
                al[mt][2] = *(const uint32_t*)(sAl + r * KS_STRIDE + cofs + 8);
                al[mt][3] = *(const uint32_t*)(sAl + (r + 8) * KS_STRIDE + cofs + 8);
            }
            #pragma unroll
            for (int nt = 0; nt < 8; nt++) {
                int cc = n_off + nt * 8 + (lane >> 2);
                int cofs = ks + (lane & 3) * 2;
                uint32_t bh0 = *(const uint32_t*)(sBh + cc * KS_STRIDE + cofs);
                uint32_t bh1 = *(const uint32_t*)(sBh + cc * KS_STRIDE + cofs + 8);
                uint32_t bl0 = *(const uint32_t*)(sBl + cc * KS_STRIDE + cofs);
                uint32_t bl1 = *(const uint32_t*)(sBl + cc * KS_STRIDE + cofs + 8);
                #pragma unroll
                for (int mt = 0; mt < 2; mt++) {
                    mma_bf16(acc[mt][nt], ah[mt], bh0, bh1);
                    mma_bf16(acc[mt][nt], al[mt], bh0, bh1);
                    mma_bf16(acc[mt][nt], ah[mt], bl0, bl1);
                }
            }
        }
        __syncthreads();
    }

    #pragma unroll
    for (int mt = 0; mt < 2; mt++) {
        int row = row0 + m_off + mt * 16 + (lane >> 2);
        #pragma unroll
        for (int nt = 0; nt < 8; nt++) {
            int col = colbase + n_off + nt * 8 + (lane & 3) * 2;
            float b0 = bias[col], b1 = bias[col + 1];
            if (row < M) {
                float2 o;
                o.x = acc[mt][nt][0] + b0; o.y = acc[mt][nt][1] + b1;
                o.x = o.x > 0.f ? o.x : 0.f;
                o.y = o.y > 0.f ? o.y : 0.f;
                *(float2*)(C + (size_t)row * 256 + col) = o;
            }
            if (row + 8 < M) {
                float2 o;
                o.x = acc[mt][nt][2] + b0; o.y = acc[mt][nt][3] + b1;
                o.x = o.x > 0.f ? o.x : 0.f;
                o.y = o.y > 0.f ? o.y : 0.f;
                *(float2*)(C + (size_t)(row + 8) * 256 + col) = o;
            }
        }
    }
}

// ---------------- pooling + heads ----------------
__device__ __forceinline__ int lower_bound_i(const int* __restrict__ a, int n, int key) {
    int lo = 0, hi = n;
    while (lo < hi) {
        int mid = (lo + hi) >> 1;
        if (a[mid] < key) lo = mid + 1; else hi = mid;
    }
    return lo;
}
__global__ __launch_bounds__(256)
void pool_heads_kernel(const float* __restrict__ h, const int* __restrict__ batch,
                       const float* __restrict__ Wmu, const float* __restrict__ bmu,
                       const float* __restrict__ Wlv, const float* __restrict__ blv,
                       float* __restrict__ out, int n, int g_total) {
    int g = blockIdx.x;
    __shared__ float hg[256];
    int lo = lower_bound_i(batch, n, g);
    int hi = lower_bound_i(batch, n, g + 1);
    int tid = threadIdx.x;
    float s = 0.f;
    for (int i = lo; i < hi; i++) s += h[(size_t)i * 256 + tid];
    float cnt = (float)(hi - lo);
    hg[tid] = s / fmaxf(cnt, 1.0f);
    __syncthreads();
    if (tid < 64) {
        float m = bmu[tid];
        #pragma unroll 8
        for (int k = 0; k < 256; k++) m = fmaf(hg[k], Wmu[k * 64 + tid], m);
        out[g * 64 + tid] = m;
    } else if (tid < 128) {
        int t = tid - 64;
        float m = blv[t];
        #pragma unroll 8
        for (int k = 0; k < 256; k++) m = fmaf(hg[k], Wlv[k * 64 + t], m);
        out[(size_t)g_total * 64 + g * 64 + t] = m;
    }
}

// ---------------- launch ----------------
extern "C" void kernel_launch(void* const* d_in, const int* in_sizes, int n_in,
                              void* d_out, int out_size) {
    const float* x     = (const float*)d_in[0];
    const int*   ei    = (const int*)d_in[1];
    const int*   batch = (const int*)d_in[2];
    int wi = (n_in >= 12) ? 4 : 3;
    const float* W1  = (const float*)d_in[wi + 0];
    const float* b1  = (const float*)d_in[wi + 1];
    const float* W2  = (const float*)d_in[wi + 2];
    const float* b2  = (const float*)d_in[wi + 3];
    const float* Wmu = (const float*)d_in[wi + 4];
    const float* bmu = (const float*)d_in[wi + 5];
    const float* Wlv = (const float*)d_in[wi + 6];
    const float* blv = (const float*)d_in[wi + 7];
    float* out = (float*)d_out;

    int n = in_sizes[0] / 128;
    int e = in_sizes[1] / 2;
    int g = out_size / 128;

    static float* p_agg = nullptr;
    static float* p_h = nullptr;
    static __nv_bfloat16* p_w1h = nullptr; static __nv_bfloat16* p_w1l = nullptr;
    static __nv_bfloat16* p_w2h = nullptr; static __nv_bfloat16* p_w2l = nullptr;
    if (!p_agg) {
        cudaGetSymbolAddress((void**)&p_agg, g_agg);
        cudaGetSymbolAddress((void**)&p_h, g_h);
        cudaGetSymbolAddress((void**)&p_w1h, g_W1h);
        cudaGetSymbolAddress((void**)&p_w1l, g_W1l);
        cudaGetSymbolAddress((void**)&p_w2h, g_W2h);
        cudaGetSymbolAddress((void**)&p_w2l, g_W2l);
    }

    int nb = (n + 1023) / 1024;
    int setup_elems = (n > 256 * 256) ? n : 256 * 256;

    setup_kernel<<<(setup_elems + 255) / 256, 256>>>(W1, W2, p_w1h, p_w1l, p_w2h, p_w2l, n);
    if ((e & 3) == 0) hist4_kernel<<<(e / 4 + 255) / 256, 256>>>(ei, e);
    else              hist1_kernel<<<(e + 255) / 256, 256>>>(ei, e);
    scan1_kernel<<<nb, 1024>>>(n);
    scan3_kernel<<<(n + 255) / 256, 256>>>(n, e);
    if ((e & 3) == 0) fill4_kernel<<<(e / 4 + 255) / 256, 256>>>(ei, e);
    else              fill1_kernel<<<(e + 255) / 256, 256>>>(ei, e);

    agg_kernel<128><<<(n + 7) / 8, 256>>>(x, p_agg, n);
    gemm_mma<128><<<dim3((n + 127) / 128, 2), 256>>>(p_agg, p_w1h, p_w1l, b1, p_h, n);
    agg_kernel<256><<<(n + 7) / 8, 256>>>(p_h, p_agg, n);
    gemm_mma<256><<<dim3((n + 127) / 128, 2), 256>>>(p_agg, p_w2h, p_w2l, b2, p_h, n);
    pool_heads_kernel<<<g, 256>>>(p_h, batch, Wmu, bmu, Wlv, blv, out, n, g);
}

// round 7
// speedup vs baseline: 1.5719x; 1.0955x over previous
#include <cuda_runtime.h>
#include <cuda_bf16.h>
#include <cuda_fp16.h>
#include <stdint.h>

#define MAX_N 50000
#define MAX_E 800000
#define HD    256

// ---------------- scratch ----------------
__device__ int   g_deg[MAX_N];
__device__ int   g_rowptr[MAX_N + 1];
__device__ int   g_cursor[MAX_N];
__device__ int   g_esrc[MAX_E];
__device__ float g_dinv[MAX_N];
__device__ int   g_bsum[64];
__device__ float g_agg[(size_t)MAX_N * HD];
__device__ float g_h[(size_t)MAX_N * HD];
__device__ __align__(16) __half g_x16[(size_t)MAX_N * 128];
__device__ __align__(16) __half g_h16[(size_t)MAX_N * 256];
// pre-transposed + bf16-split weights, layout [n][k]
__device__ __nv_bfloat16 g_W1h[256 * 128];
__device__ __nv_bfloat16 g_W1l[256 * 128];
__device__ __nv_bfloat16 g_W2h[256 * 256];
__device__ __nv_bfloat16 g_W2l[256 * 256];

// ---------------- fused setup: zero deg + weight split + x->fp16 ----------
__global__ void setup_kernel(const float* __restrict__ x,
                             const float* __restrict__ W1, const float* __restrict__ W2,
                             __nv_bfloat16* __restrict__ W1h, __nv_bfloat16* __restrict__ W1l,
                             __nv_bfloat16* __restrict__ W2h, __nv_bfloat16* __restrict__ W2l,
                             __half* __restrict__ x16, int n) {
    int i = blockIdx.x * blockDim.x + threadIdx.x;
    if (i < n) g_deg[i] = 0;
    if (i < 256 * 128) {
        int nn = i >> 7, k = i & 127;
        float w = W1[k * 256 + nn];
        __nv_bfloat16 h = __float2bfloat16_rn(w);
        W1h[i] = h;
        W1l[i] = __float2bfloat16_rn(w - __bfloat162float(h));
    }
    if (i < 256 * 256) {
        int nn = i >> 8, k = i & 255;
        float w = W2[k * 256 + nn];
        __nv_bfloat16 h = __float2bfloat16_rn(w);
        W2h[i] = h;
        W2l[i] = __float2bfloat16_rn(w - __bfloat162float(h));
    }
    if (i < n * 32) {   // n*128 floats as float4 chunks
        float4 v = ((const float4*)x)[i];
        uint2 o;
        __half2 p0 = __floats2half2_rn(v.x, v.y);
        __half2 p1 = __floats2half2_rn(v.z, v.w);
        o.x = *(uint32_t*)&p0;
        o.y = *(uint32_t*)&p1;
        ((uint2*)x16)[i] = o;
    }
}

// MLP=4 histogram over dst
__global__ void hist4_kernel(const int* __restrict__ ei, int e) {
    int i = (blockIdx.x * blockDim.x + threadIdx.x) * 4;
    if (i + 3 < e) {
        int4 d = *(const int4*)(ei + e + i);
        atomicAdd(&g_deg[d.x], 1);
        atomicAdd(&g_deg[d.y], 1);
        atomicAdd(&g_deg[d.z], 1);
        atomicAdd(&g_deg[d.w], 1);
    } else {
        for (int j = i; j < e; j++) atomicAdd(&g_deg[ei[e + j]], 1);
    }
}
__global__ void hist1_kernel(const int* __restrict__ ei, int e) {
    int i = blockIdx.x * blockDim.x + threadIdx.x;
    if (i < e) atomicAdd(&g_deg[ei[e + i]], 1);
}

// phase 1: per-block (1024) local inclusive scan of deg; also dinv
__global__ __launch_bounds__(1024)
void scan1_kernel(int n) {
    __shared__ int sh[1024];
    int tid = threadIdx.x;
    int i = blockIdx.x * 1024 + tid;
    int v = (i < n) ? g_deg[i] : 0;
    if (i < n) g_dinv[i] = rsqrtf((float)(v + 1));
    sh[tid] = v;
    __syncthreads();
    #pragma unroll
    for (int d = 1; d < 1024; d <<= 1) {
        int t = (tid >= d) ? sh[tid - d] : 0;
        __syncthreads();
        sh[tid] += t;
        __syncthreads();
    }
    if (i < n) g_rowptr[i] = sh[tid];
    if (tid == 1023) g_bsum[blockIdx.x] = sh[1023];
}
// phase 2 (fused): rowptr/cursor = inline block-offset + local exclusive
__global__ void scan3_kernel(int n, int e) {
    int win = blockIdx.x >> 2;
    int off = 0;
    for (int j = 0; j < win; j++) off += g_bsum[j];
    int i = blockIdx.x * blockDim.x + threadIdx.x;
    if (i < n) {
        int r = off + g_rowptr[i] - g_deg[i];
        g_rowptr[i] = r;
        g_cursor[i] = r;
    }
    if (i == 0) g_rowptr[n] = e;
}

// MLP=4 CSR bucket fill
__global__ void fill4_kernel(const int* __restrict__ ei, int e) {
    int i = (blockIdx.x * blockDim.x + threadIdx.x) * 4;
    if (i + 3 < e) {
        int4 s = *(const int4*)(ei + i);
        int4 d = *(const int4*)(ei + e + i);
        int p0 = atomicAdd(&g_cursor[d.x], 1);
        int p1 = atomicAdd(&g_cursor[d.y], 1);
        int p2 = atomicAdd(&g_cursor[d.z], 1);
        int p3 = atomicAdd(&g_cursor[d.w], 1);
        g_esrc[p0] = s.x; g_esrc[p1] = s.y; g_esrc[p2] = s.z; g_esrc[p3] = s.w;
    } else {
        for (int j = i; j < e; j++) {
            int src = ei[j];
            int pos = atomicAdd(&g_cursor[ei[e + j]], 1);
            g_esrc[pos] = src;
        }
    }
}
__global__ void fill1_kernel(const int* __restrict__ ei, int e) {
    int i = blockIdx.x * blockDim.x + threadIdx.x;
    if (i < e) {
        int src = ei[i];
        int pos = atomicAdd(&g_cursor[ei[e + i]], 1);
        g_esrc[pos] = src;
    }
}

// ---------------- fp16 aggregation (warp-per-node gather, unroll-2) --------
// out[i] = di*(di*x[i] + sum w_s x[s]); x rows fp16, accum fp32, out fp32.
template <int F>   // 128 or 256
__global__ void agg_f16_kernel(const __half* __restrict__ xh, float* __restrict__ out, int n) {
    int warp = blockIdx.x * (blockDim.x >> 5) + (threadIdx.x >> 5);
    int lane = threadIdx.x & 31;
    if (warp >= n) return;
    constexpr int VH = F / 32;   // halves per lane: 4 or 8
    constexpr int V2 = VH / 2;   // 32-bit words per lane: 2 or 4
    float di = g_dinv[warp];
    float acc[VH];
    const uint32_t* __restrict__ xw = (const uint32_t*)xh;
    // self term
    {
        #pragma unroll
        for (int v = 0; v < V2; v++) {
            uint32_t u = xw[(size_t)warp * (F / 2) + lane * V2 + v];
            float2 t = __half22float2(*(__half2*)&u);
            acc[2 * v] = di * t.x;
            acc[2 * v + 1] = di * t.y;
        }
    }
    int beg = g_rowptr[warp], end = g_rowptr[warp + 1];
    int e = beg;
    for (; e + 1 < end; e += 2) {
        int s0 = g_esrc[e], s1 = g_esrc[e + 1];
        float w0 = g_dinv[s0], w1 = g_dinv[s1];
        uint32_t u0[V2], u1[V2];
        if constexpr (V2 == 4) {
            uint4 a = *(const uint4*)(xw + (size_t)s0 * (F / 2) + lane * 4);
            uint4 b = *(const uint4*)(xw + (size_t)s1 * (F / 2) + lane * 4);
            u0[0] = a.x; u0[1] = a.y; u0[2] = a.z; u0[3] = a.w;
            u1[0] = b.x; u1[1] = b.y; u1[2] = b.z; u1[3] = b.w;
        } else {
            uint2 a = *(const uint2*)(xw + (size_t)s0 * (F / 2) + lane * 2);
            uint2 b = *(const uint2*)(xw + (size_t)s1 * (F / 2) + lane * 2);
            u0[0] = a.x; u0[1] = a.y;
            u1[0] = b.x; u1[1] = b.y;
        }
        #pragma unroll
        for (int v = 0; v < V2; v++) {
            float2 t0 = __half22float2(*(__half2*)&u0[v]);
            float2 t1 = __half22float2(*(__half2*)&u1[v]);
            acc[2 * v]     = fmaf(w0, t0.x, acc[2 * v]);
            acc[2 * v + 1] = fmaf(w0, t0.y, acc[2 * v + 1]);
            acc[2 * v]     = fmaf(w1, t1.x, acc[2 * v]);
            acc[2 * v + 1] = fmaf(w1, t1.y, acc[2 * v + 1]);
        }
    }
    if (e < end) {
        int s = g_esrc[e];
        float w = g_dinv[s];
        #pragma unroll
        for (int v = 0; v < V2; v++) {
            uint32_t u = xw[(size_t)s * (F / 2) + lane * V2 + v];
            float2 t = __half22float2(*(__half2*)&u);
            acc[2 * v]     = fmaf(w, t.x, acc[2 * v]);
            acc[2 * v + 1] = fmaf(w, t.y, acc[2 * v + 1]);
        }
    }
    float* op = out + (size_t)warp * F + lane * VH;
    #pragma unroll
    for (int v = 0; v < VH / 4; v++) {
        float4 r;
        r.x = di * acc[4 * v + 0];
        r.y = di * acc[4 * v + 1];
        r.z = di * acc[4 * v + 2];
        r.w = di * acc[4 * v + 3];
        *(float4*)(op + 4 * v) = r;
    }
}

// ---------------- tensor GEMM via mma.sync (occ-2 proven config) ----------
__device__ __forceinline__ void mma_bf16(float* c, const uint32_t* a, uint32_t b0, uint32_t b1) {
    asm volatile(
        "mma.sync.aligned.m16n8k16.row.col.f32.bf16.bf16.f32 "
        "{%0,%1,%2,%3}, {%4,%5,%6,%7}, {%8,%9}, {%0,%1,%2,%3};"
        : "+f"(c[0]), "+f"(c[1]), "+f"(c[2]), "+f"(c[3])
        : "r"(a[0]), "r"(a[1]), "r"(a[2]), "r"(a[3]), "r"(b0), "r"(b1));
}

#define KC 32
#define KS_STRIDE 40

// HOUT=1: write fp16 to C16; HOUT=0: write fp32 to C.
template <int K, int HOUT>
__global__ __launch_bounds__(256, 2)
void gemm_mma(const float* __restrict__ A, const __nv_bfloat16* __restrict__ Wh,
              const __nv_bfloat16* __restrict__ Wl, const float* __restrict__ bias,
              float* __restrict__ C, __half* __restrict__ C16, int M) {
    __shared__ __nv_bfloat16 sAh[128 * KS_STRIDE];
    __shared__ __nv_bfloat16 sAl[128 * KS_STRIDE];
    __shared__ __nv_bfloat16 sBh[128 * KS_STRIDE];
    __shared__ __nv_bfloat16 sBl[128 * KS_STRIDE];

    const int tid = threadIdx.x;
    const int wid = tid >> 5;
    const int lane = tid & 31;
    const int row0 = blockIdx.x * 128;
    const int colbase = blockIdx.y * 128;
    const int m_off = (wid & 3) * 32;
    const int n_off = (wid >> 2) * 64;

    float acc[2][8][4];
    #pragma unroll
    for (int mt = 0; mt < 2; mt++)
        #pragma unroll
        for (int nt = 0; nt < 8; nt++)
            #pragma unroll
            for (int q = 0; q < 4; q++) acc[mt][nt][q] = 0.f;

    for (int k0 = 0; k0 < K; k0 += KC) {
        #pragma unroll
        for (int it = 0; it < 4; it++) {
            int i = tid + it * 256;
            int r = i >> 3;
            int q = (i & 7) * 4;
            float4 v = make_float4(0.f, 0.f, 0.f, 0.f);
            if (row0 + r < M)
                v = *(const float4*)(A + (size_t)(row0 + r) * K + k0 + q);
            float hx = __bfloat162float(__float2bfloat16_rn(v.x));
            float hy = __bfloat162float(__float2bfloat16_rn(v.y));
            float hz = __bfloat162float(__float2bfloat16_rn(v.z));
            float hw = __bfloat162float(__float2bfloat16_rn(v.w));
            __nv_bfloat162* ph = (__nv_bfloat162*)(sAh + r * KS_STRIDE + q);
            __nv_bfloat162* pl = (__nv_bfloat162*)(sAl + r * KS_STRIDE + q);
            ph[0] = __floats2bfloat162_rn(hx, hy);
            ph[1] = __floats2bfloat162_rn(hz, hw);
            pl[0] = __floats2bfloat162_rn(v.x - hx, v.y - hy);
            pl[1] = __floats2bfloat162_rn(v.z - hz, v.w - hw);
        }
        #pragma unroll
        for (int it = 0; it < 4; it++) {
            int i = tid + it * 256;
            int nn = i >> 3;
            int q = (i & 7) * 4;
            const uint2* gh = (const uint2*)(Wh + (size_t)(colbase + nn) * K + k0 + q);
            const uint2* gl = (const uint2*)(Wl + (size_t)(colbase + nn) * K + k0 + q);
            *(uint2*)(sBh + nn * KS_STRIDE + q) = *gh;
            *(uint2*)(sBl + nn * KS_STRIDE + q) = *gl;
        }
        __syncthreads();

        #pragma unroll
        for (int ks = 0; ks < KC; ks += 16) {
            uint32_t ah[2][4], al[2][4];
            #pragma unroll
            for (int mt = 0; mt < 2; mt++) {
                int r = m_off + mt * 16 + (lane >> 2);
                int cofs = ks + (lane & 3) * 2;
                ah[mt][0] = *(const uint32_t*)(sAh + r * KS_STRIDE + cofs);
                ah[mt][1] = *(const uint32_t*)(sAh + (r + 8) * KS_STRIDE + cofs);
                ah[mt][2] = *(const uint32_t*)(sAh + r * KS_STRIDE + cofs + 8);
                ah[mt][3] = *(const uint32_t*)(sAh + (r + 8) * KS_STRIDE + cofs + 8);
                al[mt][0] = *(const uint32_t*)(sAl + r * KS_STRIDE + cofs);
                al[mt][1] = *(const uint32_t*)(sAl + (r + 8) * KS_STRIDE + cofs);
                al[mt][2] = *(const uint32_t*)(sAl + r * KS_STRIDE + cofs + 8);
                al[mt][3] = *(const uint32_t*)(sAl + (r + 8) * KS_STRIDE + cofs + 8);
            }
            #pragma unroll
            for (int nt = 0; nt < 8; nt++) {
                int cc = n_off + nt * 8 + (lane >> 2);
                int cofs = ks + (lane & 3) * 2;
                uint32_t bh0 = *(const uint32_t*)(sBh + cc * KS_STRIDE + cofs);
                uint32_t bh1 = *(const uint32_t*)(sBh + cc * KS_STRIDE + cofs + 8);
                uint32_t bl0 = *(const uint32_t*)(sBl + cc * KS_STRIDE + cofs);
                uint32_t bl1 = *(const uint32_t*)(sBl + cc * KS_STRIDE + cofs + 8);
                #pragma unroll
                for (int mt = 0; mt < 2; mt++) {
                    mma_bf16(acc[mt][nt], ah[mt], bh0, bh1);
                    mma_bf16(acc[mt][nt], al[mt], bh0, bh1);
                    mma_bf16(acc[mt][nt], ah[mt], bl0, bl1);
                }
            }
        }
        __syncthreads();
    }

    #pragma unroll
    for (int mt = 0; mt < 2; mt++) {
        int row = row0 + m_off + mt * 16 + (lane >> 2);
        #pragma unroll
        for (int nt = 0; nt < 8; nt++) {
            int col = colbase + n_off + nt * 8 + (lane & 3) * 2;
            float b0 = bias[col], b1 = bias[col + 1];
            float ox0 = acc[mt][nt][0] + b0, oy0 = acc[mt][nt][1] + b1;
            float ox1 = acc[mt][nt][2] + b0, oy1 = acc[mt][nt][3] + b1;
            ox0 = ox0 > 0.f ? ox0 : 0.f; oy0 = oy0 > 0.f ? oy0 : 0.f;
            ox1 = ox1 > 0.f ? ox1 : 0.f; oy1 = oy1 > 0.f ? oy1 : 0.f;
            if (HOUT) {
                if (row < M) {
                    __half2 p = __floats2half2_rn(ox0, oy0);
                    *(__half2*)(C16 + (size_t)row * 256 + col) = p;
                }
                if (row + 8 < M) {
                    __half2 p = __floats2half2_rn(ox1, oy1);
                    *(__half2*)(C16 + (size_t)(row + 8) * 256 + col) = p;
                }
            } else {
                if (row < M)
                    *(float2*)(C + (size_t)row * 256 + col) = make_float2(ox0, oy0);
                if (row + 8 < M)
                    *(float2*)(C + (size_t)(row + 8) * 256 + col) = make_float2(ox1, oy1);
            }
        }
    }
}

// ---------------- pooling + heads ----------------
__device__ __forceinline__ int lower_bound_i(const int* __restrict__ a, int n, int key) {
    int lo = 0, hi = n;
    while (lo < hi) {
        int mid = (lo + hi) >> 1;
        if (a[mid] < key) lo = mid + 1; else hi = mid;
    }
    return lo;
}
__global__ __launch_bounds__(256)
void pool_heads_kernel(const float* __restrict__ h, const int* __restrict__ batch,
                       const float* __restrict__ Wmu, const float* __restrict__ bmu,
                       const float* __restrict__ Wlv, const float* __restrict__ blv,
                       float* __restrict__ out, int n, int g_total) {
    int g = blockIdx.x;
    __shared__ float hg[256];
    int lo = lower_bound_i(batch, n, g);
    int hi = lower_bound_i(batch, n, g + 1);
    int tid = threadIdx.x;
    float s = 0.f;
    for (int i = lo; i < hi; i++) s += h[(size_t)i * 256 + tid];
    float cnt = (float)(hi - lo);
    hg[tid] = s / fmaxf(cnt, 1.0f);
    __syncthreads();
    if (tid < 64) {
        float m = bmu[tid];
        #pragma unroll 8
        for (int k = 0; k < 256; k++) m = fmaf(hg[k], Wmu[k * 64 + tid], m);
        out[g * 64 + tid] = m;
    } else if (tid < 128) {
        int t = tid - 64;
        float m = blv[t];
        #pragma unroll 8
        for (int k = 0; k < 256; k++) m = fmaf(hg[k], Wlv[k * 64 + t], m);
        out[(size_t)g_total * 64 + g * 64 + t] = m;
    }
}

// ---------------- launch ----------------
extern "C" void kernel_launch(void* const* d_in, const int* in_sizes, int n_in,
                              void* d_out, int out_size) {
    const float* x     = (const float*)d_in[0];
    const int*   ei    = (const int*)d_in[1];
    const int*   batch = (const int*)d_in[2];
    int wi = (n_in >= 12) ? 4 : 3;
    const float* W1  = (const float*)d_in[wi + 0];
    const float* b1  = (const float*)d_in[wi + 1];
    const float* W2  = (const float*)d_in[wi + 2];
    const float* b2  = (const float*)d_in[wi + 3];
    const float* Wmu = (const float*)d_in[wi + 4];
    const float* bmu = (const float*)d_in[wi + 5];
    const float* Wlv = (const float*)d_in[wi + 6];
    const float* blv = (const float*)d_in[wi + 7];
    float* out = (float*)d_out;

    int n = in_sizes[0] / 128;
    int e = in_sizes[1] / 2;
    int g = out_size / 128;

    static float* p_agg = nullptr;
    static float* p_h = nullptr;
    static __half* p_x16 = nullptr;
    static __half* p_h16 = nullptr;
    static __nv_bfloat16* p_w1h = nullptr; static __nv_bfloat16* p_w1l = nullptr;
    static __nv_bfloat16* p_w2h = nullptr; static __nv_bfloat16* p_w2l = nullptr;
    if (!p_agg) {
        cudaGetSymbolAddress((void**)&p_agg, g_agg);
        cudaGetSymbolAddress((void**)&p_h, g_h);
        cudaGetSymbolAddress((void**)&p_x16, g_x16);
        cudaGetSymbolAddress((void**)&p_h16, g_h16);
        cudaGetSymbolAddress((void**)&p_w1h, g_W1h);
        cudaGetSymbolAddress((void**)&p_w1l, g_W1l);
        cudaGetSymbolAddress((void**)&p_w2h, g_W2h);
        cudaGetSymbolAddress((void**)&p_w2l, g_W2l);
    }

    int nb = (n + 1023) / 1024;
    int setup_elems = n * 32;                     // covers x-convert, weights, deg
    if (setup_elems < 256 * 256) setup_elems = 256 * 256;

    setup_kernel<<<(setup_elems + 255) / 256, 256>>>(x, W1, W2, p_w1h, p_w1l, p_w2h, p_w2l, p_x16, n);
    if ((e & 3) == 0) hist4_kernel<<<(e / 4 + 255) / 256, 256>>>(ei, e);
    else              hist1_kernel<<<(e + 255) / 256, 256>>>(ei, e);
    scan1_kernel<<<nb, 1024>>>(n);
    scan3_kernel<<<(n + 255) / 256, 256>>>(n, e);
    if ((e & 3) == 0) fill4_kernel<<<(e / 4 + 255) / 256, 256>>>(ei, e);
    else              fill1_kernel<<<(e + 255) / 256, 256>>>(ei, e);

    agg_f16_kernel<128><<<(n + 7) / 8, 256>>>(p_x16, p_agg, n);
    gemm_mma<128, 1><<<dim3((n + 127) / 128, 2), 256>>>(p_agg, p_w1h, p_w1l, b1, nullptr, p_h16, n);
    agg_f16_kernel<256><<<(n + 7) / 8, 256>>>(p_h16, p_agg, n);
    gemm_mma<256, 0><<<dim3((n + 127) / 128, 2), 256>>>(p_agg, p_w2h, p_w2l, b2, p_h, nullptr, n);
    pool_heads_kernel<<<g, 256>>>(p_h, batch, Wmu, bmu, Wlv, blv, out, n, g);
}

// round 8
// speedup vs baseline: 1.7485x; 1.1124x over previous
#include <cuda_runtime.h>
#include <cuda_bf16.h>
#include <cuda_fp16.h>
#include <stdint.h>

#define MAX_N 50000
#define MAX_E 800000
#define HD    256

// ---------------- scratch ----------------
__device__ int   g_deg[MAX_N];
__device__ int   g_rowptr[MAX_N + 1];
__device__ int   g_cursor[MAX_N];
__device__ int   g_esrc[MAX_E];
__device__ float g_dinv[MAX_N];
__device__ int   g_bsum[64];
__device__ __align__(16) __half g_x16[(size_t)MAX_N * 128];
__device__ __align__(16) __half g_a16[(size_t)MAX_N * 256];   // agg output (GEMM A)
__device__ __align__(16) __half g_h16[(size_t)MAX_N * 256];   // GEMM output
// fp16 weights, transposed [n][k]; Wl pre-scaled by 512 (subnormal-safe)
__device__ __half g_W1h[256 * 128];
__device__ __half g_W1l[256 * 128];
__device__ __half g_W2h[256 * 256];
__device__ __half g_W2l[256 * 256];

// ---------------- fused setup: zero deg + weight split + x->fp16 ----------
__global__ void setup_kernel(const float* __restrict__ x,
                             const float* __restrict__ W1, const float* __restrict__ W2,
                             __half* __restrict__ W1h, __half* __restrict__ W1l,
                             __half* __restrict__ W2h, __half* __restrict__ W2l,
                             __half* __restrict__ x16, int n) {
    int i = blockIdx.x * blockDim.x + threadIdx.x;
    if (i < n) g_deg[i] = 0;
    if (i < 256 * 128) {
        int nn = i >> 7, k = i & 127;
        float w = W1[k * 256 + nn];
        __half h = __float2half_rn(w);
        W1h[i] = h;
        W1l[i] = __float2half_rn((w - __half2float(h)) * 512.0f);
    }
    if (i < 256 * 256) {
        int nn = i >> 8, k = i & 255;
        float w = W2[k * 256 + nn];
        __half h = __float2half_rn(w);
        W2h[i] = h;
        W2l[i] = __float2half_rn((w - __half2float(h)) * 512.0f);
    }
    if (i < n * 32) {   // n*128 floats as float4 chunks
        float4 v = ((const float4*)x)[i];
        uint2 o;
        __half2 p0 = __floats2half2_rn(v.x, v.y);
        __half2 p1 = __floats2half2_rn(v.z, v.w);
        o.x = *(uint32_t*)&p0;
        o.y = *(uint32_t*)&p1;
        ((uint2*)x16)[i] = o;
    }
}

// MLP=4 histogram over dst
__global__ void hist4_kernel(const int* __restrict__ ei, int e) {
    int i = (blockIdx.x * blockDim.x + threadIdx.x) * 4;
    if (i + 3 < e) {
        int4 d = *(const int4*)(ei + e + i);
        atomicAdd(&g_deg[d.x], 1);
        atomicAdd(&g_deg[d.y], 1);
        atomicAdd(&g_deg[d.z], 1);
        atomicAdd(&g_deg[d.w], 1);
    } else {
        for (int j = i; j < e; j++) atomicAdd(&g_deg[ei[e + j]], 1);
    }
}
__global__ void hist1_kernel(const int* __restrict__ ei, int e) {
    int i = blockIdx.x * blockDim.x + threadIdx.x;
    if (i < e) atomicAdd(&g_deg[ei[e + i]], 1);
}

// phase 1: per-block (1024) local inclusive scan of deg; also dinv
__global__ __launch_bounds__(1024)
void scan1_kernel(int n) {
    __shared__ int sh[1024];
    int tid = threadIdx.x;
    int i = blockIdx.x * 1024 + tid;
    int v = (i < n) ? g_deg[i] : 0;
    if (i < n) g_dinv[i] = rsqrtf((float)(v + 1));
    sh[tid] = v;
    __syncthreads();
    #pragma unroll
    for (int d = 1; d < 1024; d <<= 1) {
        int t = (tid >= d) ? sh[tid - d] : 0;
        __syncthreads();
        sh[tid] += t;
        __syncthreads();
    }
    if (i < n) g_rowptr[i] = sh[tid];
    if (tid == 1023) g_bsum[blockIdx.x] = sh[1023];
}
// phase 2 (fused): rowptr/cursor = inline block-offset + local exclusive
__global__ void scan3_kernel(int n, int e) {
    int win = blockIdx.x >> 2;
    int off = 0;
    for (int j = 0; j < win; j++) off += g_bsum[j];
    int i = blockIdx.x * blockDim.x + threadIdx.x;
    if (i < n) {
        int r = off + g_rowptr[i] - g_deg[i];
        g_rowptr[i] = r;
        g_cursor[i] = r;
    }
    if (i == 0) g_rowptr[n] = e;
}

// MLP=4 CSR bucket fill
__global__ void fill4_kernel(const int* __restrict__ ei, int e) {
    int i = (blockIdx.x * blockDim.x + threadIdx.x) * 4;
    if (i + 3 < e) {
        int4 s = *(const int4*)(ei + i);
        int4 d = *(const int4*)(ei + e + i);
        int p0 = atomicAdd(&g_cursor[d.x], 1);
        int p1 = atomicAdd(&g_cursor[d.y], 1);
        int p2 = atomicAdd(&g_cursor[d.z], 1);
        int p3 = atomicAdd(&g_cursor[d.w], 1);
        g_esrc[p0] = s.x; g_esrc[p1] = s.y; g_esrc[p2] = s.z; g_esrc[p3] = s.w;
    } else {
        for (int j = i; j < e; j++) {
            int src = ei[j];
            int pos = atomicAdd(&g_cursor[ei[e + j]], 1);
            g_esrc[pos] = src;
        }
    }
}
__global__ void fill1_kernel(const int* __restrict__ ei, int e) {
    int i = blockIdx.x * blockDim.x + threadIdx.x;
    if (i < e) {
        int src = ei[i];
        int pos = atomicAdd(&g_cursor[ei[e + i]], 1);
        g_esrc[pos] = src;
    }
}

// ---------------- fp16 aggregation (warp-per-node gather, fp16 out) --------
template <int F>   // 128 or 256
__global__ void agg_f16_kernel(const __half* __restrict__ xh, __half* __restrict__ out, int n) {
    int warp = blockIdx.x * (blockDim.x >> 5) + (threadIdx.x >> 5);
    int lane = threadIdx.x & 31;
    if (warp >= n) return;
    constexpr int VH = F / 32;   // halves per lane: 4 or 8
    constexpr int V2 = VH / 2;   // 32-bit words per lane: 2 or 4
    float di = g_dinv[warp];
    float acc[VH];
    const uint32_t* __restrict__ xw = (const uint32_t*)xh;
    {
        #pragma unroll
        for (int v = 0; v < V2; v++) {
            uint32_t u = xw[(size_t)warp * (F / 2) + lane * V2 + v];
            float2 t = __half22float2(*(__half2*)&u);
            acc[2 * v] = di * t.x;
            acc[2 * v + 1] = di * t.y;
        }
    }
    int beg = g_rowptr[warp], end = g_rowptr[warp + 1];
    int e = beg;
    for (; e + 1 < end; e += 2) {
        int s0 = g_esrc[e], s1 = g_esrc[e + 1];
        float w0 = g_dinv[s0], w1 = g_dinv[s1];
        uint32_t u0[V2], u1[V2];
        if constexpr (V2 == 4) {
            uint4 a = *(const uint4*)(xw + (size_t)s0 * (F / 2) + lane * 4);
            uint4 b = *(const uint4*)(xw + (size_t)s1 * (F / 2) + lane * 4);
            u0[0] = a.x; u0[1] = a.y; u0[2] = a.z; u0[3] = a.w;
            u1[0] = b.x; u1[1] = b.y; u1[2] = b.z; u1[3] = b.w;
        } else {
            uint2 a = *(const uint2*)(xw + (size_t)s0 * (F / 2) + lane * 2);
            uint2 b = *(const uint2*)(xw + (size_t)s1 * (F / 2) + lane * 2);
            u0[0] = a.x; u0[1] = a.y;
            u1[0] = b.x; u1[1] = b.y;
        }
        #pragma unroll
        for (int v = 0; v < V2; v++) {
            float2 t0 = __half22float2(*(__half2*)&u0[v]);
            float2 t1 = __half22float2(*(__half2*)&u1[v]);
            acc[2 * v]     = fmaf(w0, t0.x, acc[2 * v]);
            acc[2 * v + 1] = fmaf(w0, t0.y, acc[2 * v + 1]);
            acc[2 * v]     = fmaf(w1, t1.x, acc[2 * v]);
            acc[2 * v + 1] = fmaf(w1, t1.y, acc[2 * v + 1]);
        }
    }
    if (e < end) {
        int s = g_esrc[e];
        float w = g_dinv[s];
        #pragma unroll
        for (int v = 0; v < V2; v++) {
            uint32_t u = xw[(size_t)s * (F / 2) + lane * V2 + v];
            float2 t = __half22float2(*(__half2*)&u);
            acc[2 * v]     = fmaf(w, t.x, acc[2 * v]);
            acc[2 * v + 1] = fmaf(w, t.y, acc[2 * v + 1]);
        }
    }
    __half2* op = (__half2*)(out + (size_t)warp * F + lane * VH);
    #pragma unroll
    for (int v = 0; v < V2; v++)
        op[v] = __floats2half2_rn(di * acc[2 * v], di * acc[2 * v + 1]);
}

// ---------------- fp16 tensor GEMM, 2-term scaled-residual split ----------
// C = relu(A @ (Wh + Wl/512) + b):  acc += Ah*Bh; acc += (Ah*2^-9)*Bl
__device__ __forceinline__ void mma_f16(float* c, const uint32_t* a, uint32_t b0, uint32_t b1) {
    asm volatile(
        "mma.sync.aligned.m16n8k16.row.col.f32.f16.f16.f32 "
        "{%0,%1,%2,%3}, {%4,%5,%6,%7}, {%8,%9}, {%0,%1,%2,%3};"
        : "+f"(c[0]), "+f"(c[1]), "+f"(c[2]), "+f"(c[3])
        : "r"(a[0]), "r"(a[1]), "r"(a[2]), "r"(a[3]), "r"(b0), "r"(b1));
}

#define KC 32
#define KS_STRIDE 40

template <int K>
__global__ __launch_bounds__(256, 2)
void gemm_f16(const __half* __restrict__ A, const __half* __restrict__ Wh,
              const __half* __restrict__ Wl, const float* __restrict__ bias,
              __half* __restrict__ C16, int M) {
    __shared__ __half sA[128 * KS_STRIDE];
    __shared__ __half sBh[128 * KS_STRIDE];
    __shared__ __half sBl[128 * KS_STRIDE];

    const int tid = threadIdx.x;
    const int wid = tid >> 5;
    const int lane = tid & 31;
    const int row0 = blockIdx.x * 128;
    const int colbase = blockIdx.y * 128;
    const int m_off = (wid & 3) * 32;
    const int n_off = (wid >> 2) * 64;
    const __half2 inv512 = __half2half2(__float2half(0.001953125f));  // 2^-9

    float acc[2][8][4];
    #pragma unroll
    for (int mt = 0; mt < 2; mt++)
        #pragma unroll
        for (int nt = 0; nt < 8; nt++)
            #pragma unroll
            for (int q = 0; q < 4; q++) acc[mt][nt][q] = 0.f;

    for (int k0 = 0; k0 < K; k0 += KC) {
        // stage A (fp16 copy, 128 x 32 halves)
        #pragma unroll
        for (int it = 0; it < 4; it++) {
            int i = tid + it * 256;
            int r = i >> 3;
            int q = (i & 7) * 4;
            uint2 v = make_uint2(0u, 0u);
            if (row0 + r < M)
                v = *(const uint2*)(A + (size_t)(row0 + r) * K + k0 + q);
            *(uint2*)(sA + r * KS_STRIDE + q) = v;
        }
        // stage B (fp16 Wh/Wl copies)
        #pragma unroll
        for (int it = 0; it < 4; it++) {
            int i = tid + it * 256;
            int nn = i >> 3;
            int q = (i & 7) * 4;
            *(uint2*)(sBh + nn * KS_STRIDE + q) =
                *(const uint2*)(Wh + (size_t)(colbase + nn) * K + k0 + q);
            *(uint2*)(sBl + nn * KS_STRIDE + q) =
                *(const uint2*)(Wl + (size_t)(colbase + nn) * K + k0 + q);
        }
        __syncthreads();

        #pragma unroll
        for (int ks = 0; ks < KC; ks += 16) {
            uint32_t ah[2][4], as[2][4];
            int cofs = ks + (lane & 3) * 2;
            #pragma unroll
            for (int mt = 0; mt < 2; mt++) {
                int r = m_off + mt * 16 + (lane >> 2);
                ah[mt][0] = *(const uint32_t*)(sA + r * KS_STRIDE + cofs);
                ah[mt][1] = *(const uint32_t*)(sA + (r + 8) * KS_STRIDE + cofs);
                ah[mt][2] = *(const uint32_t*)(sA + r * KS_STRIDE + cofs + 8);
                ah[mt][3] = *(const uint32_t*)(sA + (r + 8) * KS_STRIDE + cofs + 8);
                #pragma unroll
                for (int q = 0; q < 4; q++) {
                    __half2 h = __hmul2(*(__half2*)&ah[mt][q], inv512);
                    as[mt][q] = *(uint32_t*)&h;
                }
            }
            #pragma unroll
            for (int nt = 0; nt < 8; nt++) {
                int cc = n_off + nt * 8 + (lane >> 2);
                uint32_t bh0 = *(const uint32_t*)(sBh + cc * KS_STRIDE + cofs);
                uint32_t bh1 = *(const uint32_t*)(sBh + cc * KS_STRIDE + cofs + 8);
                uint32_t bl0 = *(const uint32_t*)(sBl + cc * KS_STRIDE + cofs);
                uint32_t bl1 = *(const uint32_t*)(sBl + cc * KS_STRIDE + cofs + 8);
                #pragma unroll
                for (int mt = 0; mt < 2; mt++) {
                    mma_f16(acc[mt][nt], ah[mt], bh0, bh1);
                    mma_f16(acc[mt][nt], as[mt], bl0, bl1);
                }
            }
        }
        __syncthreads();
    }

    // epilogue: bias + relu + fp16 store
    #pragma unroll
    for (int mt = 0; mt < 2; mt++) {
        int row = row0 + m_off + mt * 16 + (lane >> 2);
        #pragma unroll
        for (int nt = 0; nt < 8; nt++) {
            int col = colbase + n_off + nt * 8 + (lane & 3) * 2;
            float b0 = bias[col], b1 = bias[col + 1];
            float ox0 = acc[mt][nt][0] + b0, oy0 = acc[mt][nt][1] + b1;
            float ox1 = acc[mt][nt][2] + b0, oy1 = acc[mt][nt][3] + b1;
            ox0 = ox0 > 0.f ? ox0 : 0.f; oy0 = oy0 > 0.f ? oy0 : 0.f;
            ox1 = ox1 > 0.f ? ox1 : 0.f; oy1 = oy1 > 0.f ? oy1 : 0.f;
            if (row < M)
                *(__half2*)(C16 + (size_t)row * 256 + col) = __floats2half2_rn(ox0, oy0);
            if (row + 8 < M)
                *(__half2*)(C16 + (size_t)(row + 8) * 256 + col) = __floats2half2_rn(ox1, oy1);
        }
    }
}

// ---------------- pooling + heads (fp16 h input) ----------------
__device__ __forceinline__ int lower_bound_i(const int* __restrict__ a, int n, int key) {
    int lo = 0, hi = n;
    while (lo < hi) {
        int mid = (lo + hi) >> 1;
        if (a[mid] < key) lo = mid + 1; else hi = mid;
    }
    return lo;
}
__global__ __launch_bounds__(256)
void pool_heads_kernel(const __half* __restrict__ h, const int* __restrict__ batch,
                       const float* __restrict__ Wmu, const float* __restrict__ bmu,
                       const float* __restrict__ Wlv, const float* __restrict__ blv,
                       float* __restrict__ out, int n, int g_total) {
    int g = blockIdx.x;
    __shared__ float hg[256];
    int lo = lower_bound_i(batch, n, g);
    int hi = lower_bound_i(batch, n, g + 1);
    int tid = threadIdx.x;
    float s = 0.f;
    for (int i = lo; i < hi; i++) s += __half2float(h[(size_t)i * 256 + tid]);
    float cnt = (float)(hi - lo);
    hg[tid] = s / fmaxf(cnt, 1.0f);
    __syncthreads();
    if (tid < 64) {
        float m = bmu[tid];
        #pragma unroll 8
        for (int k = 0; k < 256; k++) m = fmaf(hg[k], Wmu[k * 64 + tid], m);
        out[g * 64 + tid] = m;
    } else if (tid < 128) {
        int t = tid - 64;
        float m = blv[t];
        #pragma unroll 8
        for (int k = 0; k < 256; k++) m = fmaf(hg[k], Wlv[k * 64 + t], m);
        out[(size_t)g_total * 64 + g * 64 + t] = m;
    }
}

// ---------------- launch ----------------
extern "C" void kernel_launch(void* const* d_in, const int* in_sizes, int n_in,
                              void* d_out, int out_size) {
    const float* x     = (const float*)d_in[0];
    const int*   ei    = (const int*)d_in[1];
    const int*   batch = (const int*)d_in[2];
    int wi = (n_in >= 12) ? 4 : 3;
    const float* W1  = (const float*)d_in[wi + 0];
    const float* b1  = (const float*)d_in[wi + 1];
    const float* W2  = (const float*)d_in[wi + 2];
    const float* b2  = (const float*)d_in[wi + 3];
    const float* Wmu = (const float*)d_in[wi + 4];
    const float* bmu = (const float*)d_in[wi + 5];
    const float* Wlv = (const float*)d_in[wi + 6];
    const float* blv = (const float*)d_in[wi + 7];
    float* out = (float*)d_out;

    int n = in_sizes[0] / 128;
    int e = in_sizes[1] / 2;
    int g = out_size / 128;

    static __half* p_x16 = nullptr;
    static __half* p_a16 = nullptr;
    static __half* p_h16 = nullptr;
    static __half* p_w1h = nullptr; static __half* p_w1l = nullptr;
    static __half* p_w2h = nullptr; static __half* p_w2l = nullptr;
    if (!p_x16) {
        cudaGetSymbolAddress((void**)&p_x16, g_x16);
        cudaGetSymbolAddress((void**)&p_a16, g_a16);
        cudaGetSymbolAddress((void**)&p_h16, g_h16);
        cudaGetSymbolAddress((void**)&p_w1h, g_W1h);
        cudaGetSymbolAddress((void**)&p_w1l, g_W1l);
        cudaGetSymbolAddress((void**)&p_w2h, g_W2h);
        cudaGetSymbolAddress((void**)&p_w2l, g_W2l);
    }

    int nb = (n + 1023) / 1024;
    int setup_elems = n * 32;
    if (setup_elems < 256 * 256) setup_elems = 256 * 256;

    setup_kernel<<<(setup_elems + 255) / 256, 256>>>(x, W1, W2, p_w1h, p_w1l, p_w2h, p_w2l, p_x16, n);
    if ((e & 3) == 0) hist4_kernel<<<(e / 4 + 255) / 256, 256>>>(ei, e);
    else              hist1_kernel<<<(e + 255) / 256, 256>>>(ei, e);
    scan1_kernel<<<nb, 1024>>>(n);
    scan3_kernel<<<(n + 255) / 256, 256>>>(n, e);
    if ((e & 3) == 0) fill4_kernel<<<(e / 4 + 255) / 256, 256>>>(ei, e);
    else              fill1_kernel<<<(e + 255) / 256, 256>>>(ei, e);

    agg_f16_kernel<128><<<(n + 7) / 8, 256>>>(p_x16, p_a16, n);
    gemm_f16<128><<<dim3((n + 127) / 128, 2), 256>>>(p_a16, p_w1h, p_w1l, b1, p_h16, n);
    agg_f16_kernel<256><<<(n + 7) / 8, 256>>>(p_h16, p_a16, n);
    gemm_f16<256><<<dim3((n + 127) / 128, 2), 256>>>(p_a16, p_w2h, p_w2l, b2, p_h16, n);
    pool_heads_kernel<<<g, 256>>>(p_h16, batch, Wmu, bmu, Wlv, blv, out, n, g);
}

// round 9
// speedup vs baseline: 1.8725x; 1.0709x over previous
#include <cuda_runtime.h>
#include <cuda_bf16.h>
#include <cuda_fp16.h>
#include <stdint.h>

#define MAX_N 50000
#define MAX_E 800000
#define HD    256

// ---------------- scratch ----------------
__device__ int   g_deg[MAX_N];
__device__ int   g_rowptr[MAX_N + 1];
__device__ int   g_cursor[MAX_N];
__device__ int   g_esrc[MAX_E];
__device__ float g_dinv[MAX_N];
__device__ int   g_bsum[64];
__device__ __align__(16) __half g_x16[(size_t)MAX_N * 128];
__device__ __align__(16) __half g_a16[(size_t)MAX_N * 256];
__device__ __align__(16) __half g_h16[(size_t)MAX_N * 256];
// fp16 weights, transposed [n][k]; Wl pre-scaled by 512 (subnormal-safe)
__device__ __half g_W1h[256 * 128];
__device__ __half g_W1l[256 * 128];
__device__ __half g_W2h[256 * 256];
__device__ __half g_W2l[256 * 256];

// ---------------- fused setup ----------------
__global__ void setup_kernel(const float* __restrict__ x,
                             const float* __restrict__ W1, const float* __restrict__ W2,
                             __half* __restrict__ W1h, __half* __restrict__ W1l,
                             __half* __restrict__ W2h, __half* __restrict__ W2l,
                             __half* __restrict__ x16, int n) {
    int i = blockIdx.x * blockDim.x + threadIdx.x;
    if (i < n) g_deg[i] = 0;
    if (i < 256 * 128) {
        int nn = i >> 7, k = i & 127;
        float w = W1[k * 256 + nn];
        __half h = __float2half_rn(w);
        W1h[i] = h;
        W1l[i] = __float2half_rn((w - __half2float(h)) * 512.0f);
    }
    if (i < 256 * 256) {
        int nn = i >> 8, k = i & 255;
        float w = W2[k * 256 + nn];
        __half h = __float2half_rn(w);
        W2h[i] = h;
        W2l[i] = __float2half_rn((w - __half2float(h)) * 512.0f);
    }
    if (i < n * 32) {
        float4 v = ((const float4*)x)[i];
        uint2 o;
        __half2 p0 = __floats2half2_rn(v.x, v.y);
        __half2 p1 = __floats2half2_rn(v.z, v.w);
        o.x = *(uint32_t*)&p0;
        o.y = *(uint32_t*)&p1;
        ((uint2*)x16)[i] = o;
    }
}

__global__ void hist4_kernel(const int* __restrict__ ei, int e) {
    int i = (blockIdx.x * blockDim.x + threadIdx.x) * 4;
    if (i + 3 < e) {
        int4 d = *(const int4*)(ei + e + i);
        atomicAdd(&g_deg[d.x], 1);
        atomicAdd(&g_deg[d.y], 1);
        atomicAdd(&g_deg[d.z], 1);
        atomicAdd(&g_deg[d.w], 1);
    } else {
        for (int j = i; j < e; j++) atomicAdd(&g_deg[ei[e + j]], 1);
    }
}
__global__ void hist1_kernel(const int* __restrict__ ei, int e) {
    int i = blockIdx.x * blockDim.x + threadIdx.x;
    if (i < e) atomicAdd(&g_deg[ei[e + i]], 1);
}

__global__ __launch_bounds__(1024)
void scan1_kernel(int n) {
    __shared__ int sh[1024];
    int tid = threadIdx.x;
    int i = blockIdx.x * 1024 + tid;
    int v = (i < n) ? g_deg[i] : 0;
    if (i < n) g_dinv[i] = rsqrtf((float)(v + 1));
    sh[tid] = v;
    __syncthreads();
    #pragma unroll
    for (int d = 1; d < 1024; d <<= 1) {
        int t = (tid >= d) ? sh[tid - d] : 0;
        __syncthreads();
        sh[tid] += t;
        __syncthreads();
    }
    if (i < n) g_rowptr[i] = sh[tid];
    if (tid == 1023) g_bsum[blockIdx.x] = sh[1023];
}
__global__ void scan3_kernel(int n, int e) {
    int win = blockIdx.x >> 2;
    int off = 0;
    for (int j = 0; j < win; j++) off += g_bsum[j];
    int i = blockIdx.x * blockDim.x + threadIdx.x;
    if (i < n) {
        int r = off + g_rowptr[i] - g_deg[i];
        g_rowptr[i] = r;
        g_cursor[i] = r;
    }
    if (i == 0) g_rowptr[n] = e;
}

__global__ void fill4_kernel(const int* __restrict__ ei, int e) {
    int i = (blockIdx.x * blockDim.x + threadIdx.x) * 4;
    if (i + 3 < e) {
        int4 s = *(const int4*)(ei + i);
        int4 d = *(const int4*)(ei + e + i);
        int p0 = atomicAdd(&g_cursor[d.x], 1);
        int p1 = atomicAdd(&g_cursor[d.y], 1);
        int p2 = atomicAdd(&g_cursor[d.z], 1);
        int p3 = atomicAdd(&g_cursor[d.w], 1);
        g_esrc[p0] = s.x; g_esrc[p1] = s.y; g_esrc[p2] = s.z; g_esrc[p3] = s.w;
    } else {
        for (int j = i; j < e; j++) {
            int src = ei[j];
            int pos = atomicAdd(&g_cursor[ei[e + j]], 1);
            g_esrc[pos] = src;
        }
    }
}
__global__ void fill1_kernel(const int* __restrict__ ei, int e) {
    int i = blockIdx.x * blockDim.x + threadIdx.x;
    if (i < e) {
        int src = ei[i];
        int pos = atomicAdd(&g_cursor[ei[e + i]], 1);
        g_esrc[pos] = src;
    }
}

// ---------------- fp16 aggregation ----------------
template <int F>
__global__ void agg_f16_kernel(const __half* __restrict__ xh, __half* __restrict__ out, int n) {
    int warp = blockIdx.x * (blockDim.x >> 5) + (threadIdx.x >> 5);
    int lane = threadIdx.x & 31;
    if (warp >= n) return;
    constexpr int VH = F / 32;
    constexpr int V2 = VH / 2;
    float di = g_dinv[warp];
    float acc[VH];
    const uint32_t* __restrict__ xw = (const uint32_t*)xh;
    {
        #pragma unroll
        for (int v = 0; v < V2; v++) {
            uint32_t u = xw[(size_t)warp * (F / 2) + lane * V2 + v];
            float2 t = __half22float2(*(__half2*)&u);
            acc[2 * v] = di * t.x;
            acc[2 * v + 1] = di * t.y;
        }
    }
    int beg = g_rowptr[warp], end = g_rowptr[warp + 1];
    int e = beg;
    for (; e + 1 < end; e += 2) {
        int s0 = g_esrc[e], s1 = g_esrc[e + 1];
        float w0 = g_dinv[s0], w1 = g_dinv[s1];
        uint32_t u0[V2], u1[V2];
        if constexpr (V2 == 4) {
            uint4 a = *(const uint4*)(xw + (size_t)s0 * (F / 2) + lane * 4);
            uint4 b = *(const uint4*)(xw + (size_t)s1 * (F / 2) + lane * 4);
            u0[0] = a.x; u0[1] = a.y; u0[2] = a.z; u0[3] = a.w;
            u1[0] = b.x; u1[1] = b.y; u1[2] = b.z; u1[3] = b.w;
        } else {
            uint2 a = *(const uint2*)(xw + (size_t)s0 * (F / 2) + lane * 2);
            uint2 b = *(const uint2*)(xw + (size_t)s1 * (F / 2) + lane * 2);
            u0[0] = a.x; u0[1] = a.y;
            u1[0] = b.x; u1[1] = b.y;
        }
        #pragma unroll
        for (int v = 0; v < V2; v++) {
            float2 t0 = __half22float2(*(__half2*)&u0[v]);
            float2 t1 = __half22float2(*(__half2*)&u1[v]);
            acc[2 * v]     = fmaf(w0, t0.x, acc[2 * v]);
            acc[2 * v + 1] = fmaf(w0, t0.y, acc[2 * v + 1]);
            acc[2 * v]     = fmaf(w1, t1.x, acc[2 * v]);
            acc[2 * v + 1] = fmaf(w1, t1.y, acc[2 * v + 1]);
        }
    }
    if (e < end) {
        int s = g_esrc[e];
        float w = g_dinv[s];
        #pragma unroll
        for (int v = 0; v < V2; v++) {
            uint32_t u = xw[(size_t)s * (F / 2) + lane * V2 + v];
            float2 t = __half22float2(*(__half2*)&u);
            acc[2 * v]     = fmaf(w, t.x, acc[2 * v]);
            acc[2 * v + 1] = fmaf(w, t.y, acc[2 * v + 1]);
        }
    }
    __half2* op = (__half2*)(out + (size_t)warp * F + lane * VH);
    #pragma unroll
    for (int v = 0; v < V2; v++)
        op[v] = __floats2half2_rn(di * acc[2 * v], di * acc[2 * v + 1]);
}

// ---------------- fp16 tensor GEMM: ldmatrix + cp.async pipeline ----------
__device__ __forceinline__ void mma_f16(float* c, const uint32_t* a, uint32_t b0, uint32_t b1) {
    asm volatile(
        "mma.sync.aligned.m16n8k16.row.col.f32.f16.f16.f32 "
        "{%0,%1,%2,%3}, {%4,%5,%6,%7}, {%8,%9}, {%0,%1,%2,%3};"
        : "+f"(c[0]), "+f"(c[1]), "+f"(c[2]), "+f"(c[3])
        : "r"(a[0]), "r"(a[1]), "r"(a[2]), "r"(a[3]), "r"(b0), "r"(b1));
}
__device__ __forceinline__ void ldsm4(uint32_t* r, uint32_t addr) {
    asm volatile("ldmatrix.sync.aligned.m8n8.x4.shared.b16 {%0,%1,%2,%3}, [%4];"
                 : "=r"(r[0]), "=r"(r[1]), "=r"(r[2]), "=r"(r[3]) : "r"(addr));
}
__device__ __forceinline__ void cp16(uint32_t dst, const void* src) {
    asm volatile("cp.async.cg.shared.global [%0], [%1], 16;" :: "r"(dst), "l"(src));
}
__device__ __forceinline__ uint32_t smem_u32(const void* p) {
    uint32_t a;
    asm("{.reg .u64 t; cvta.to.shared.u64 t, %1; cvt.u32.u64 %0, t;}" : "=r"(a) : "l"(p));
    return a;
}

#define KC 32
#define ROWB 80                    // bytes per smem row (32 halves + 8 pad)
#define ARRB (128 * ROWB)          // 10240 B per array
#define BUFB (3 * ARRB)            // 30720 B per buffer
#define GEMM_SMEM (2 * BUFB)       // 61440 B

template <int K>
__global__ __launch_bounds__(256, 2)
void gemm_f16(const __half* __restrict__ A, const __half* __restrict__ Wh,
              const __half* __restrict__ Wl, const float* __restrict__ bias,
              __half* __restrict__ C16, int M) {
    extern __shared__ __half smem[];
    const uint32_t sbase = smem_u32(smem);
    const int tid = threadIdx.x;
    const int wid = tid >> 5;
    const int lane = tid & 31;
    const int row0 = blockIdx.x * 128;
    const int colbase = blockIdx.y * 128;
    const int m_off = (wid & 3) * 32;
    const int n_off = (wid >> 2) * 64;
    const __half2 inv512 = __half2half2(__float2half(0.001953125f));
    constexpr int CHUNKS = K / KC;

    float acc[2][8][4];
    #pragma unroll
    for (int mt = 0; mt < 2; mt++)
        #pragma unroll
        for (int nt = 0; nt < 8; nt++)
            #pragma unroll
            for (int q = 0; q < 4; q++) acc[mt][nt][q] = 0.f;

    // stage chunk c into buffer b via cp.async (6 x 16B per thread)
    const int st_r = tid >> 2;          // 0..63 with it; full 0..127 via it*64... see below
    auto stage = [&](int c, int b) {
        int k0 = c * KC;
        uint32_t buf = sbase + b * BUFB;
        #pragma unroll
        for (int it = 0; it < 2; it++) {
            int i = tid + it * 256;     // 0..511
            int r = i >> 2;             // 0..127
            int q = (i & 3) * 8;        // halves 0,8,16,24
            int rr = row0 + r; if (rr >= M) rr = M - 1;
            cp16(buf + r * ROWB + q * 2, A + (size_t)rr * K + k0 + q);
            int nn = colbase + r;
            cp16(buf + ARRB + r * ROWB + q * 2, Wh + (size_t)nn * K + k0 + q);
            cp16(buf + 2 * ARRB + r * ROWB + q * 2, Wl + (size_t)nn * K + k0 + q);
        }
        asm volatile("cp.async.commit_group;");
    };

    // ldmatrix lane address components
    const int a_rsel = lane & 15;
    const int a_ksel = (lane >> 4) * 8;
    const int b_nsel = (lane & 7) + ((lane >> 4) << 3);
    const int b_koff = ((lane >> 3) & 1) * 8;

    auto compute = [&](int b) {
        uint32_t sa = sbase + b * BUFB;
        uint32_t sbh = sa + ARRB;
        uint32_t sbl = sa + 2 * ARRB;
        #pragma unroll
        for (int ks = 0; ks < KC; ks += 16) {
            uint32_t ah[2][4], as[2][4];
            #pragma unroll
            for (int mt = 0; mt < 2; mt++) {
                uint32_t addr = sa + (m_off + mt * 16 + a_rsel) * ROWB + (ks + a_ksel) * 2;
                ldsm4(ah[mt], addr);
                #pragma unroll
                for (int q = 0; q < 4; q++) {
                    __half2 h = __hmul2(*(__half2*)&ah[mt][q], inv512);
                    as[mt][q] = *(uint32_t*)&h;
                }
            }
            #pragma unroll
            for (int p = 0; p < 4; p++) {
                uint32_t off = (n_off + p * 16 + b_nsel) * ROWB + (ks + b_koff) * 2;
                uint32_t bh4[4], bl4[4];
                ldsm4(bh4, sbh + off);
                ldsm4(bl4, sbl + off);
                #pragma unroll
                for (int mt = 0; mt < 2; mt++) {
                    mma_f16(acc[mt][2 * p],     ah[mt], bh4[0], bh4[1]);
                    mma_f16(acc[mt][2 * p + 1], ah[mt], bh4[2], bh4[3]);
                    mma_f16(acc[mt][2 * p],     as[mt], bl4[0], bl4[1]);
                    mma_f16(acc[mt][2 * p + 1], as[mt], bl4[2], bl4[3]);
                }
            }
        }
    };

    stage(0, 0);
    asm volatile("cp.async.wait_group 0;");
    __syncthreads();
    for (int c = 0; c < CHUNKS; c++) {
        if (c + 1 < CHUNKS) stage(c + 1, (c + 1) & 1);
        compute(c & 1);
        if (c + 1 < CHUNKS) asm volatile("cp.async.wait_group 0;");
        __syncthreads();
    }

    // epilogue: bias + relu + fp16 store
    #pragma unroll
    for (int mt = 0; mt < 2; mt++) {
        int row = row0 + m_off + mt * 16 + (lane >> 2);
        #pragma unroll
        for (int nt = 0; nt < 8; nt++) {
            int col = colbase + n_off + nt * 8 + (lane & 3) * 2;
            float b0 = bias[col], b1 = bias[col + 1];
            float ox0 = acc[mt][nt][0] + b0, oy0 = acc[mt][nt][1] + b1;
            float ox1 = acc[mt][nt][2] + b0, oy1 = acc[mt][nt][3] + b1;
            ox0 = ox0 > 0.f ? ox0 : 0.f; oy0 = oy0 > 0.f ? oy0 : 0.f;
            ox1 = ox1 > 0.f ? ox1 : 0.f; oy1 = oy1 > 0.f ? oy1 : 0.f;
            if (row < M)
                *(__half2*)(C16 + (size_t)row * 256 + col) = __floats2half2_rn(ox0, oy0);
            if (row + 8 < M)
                *(__half2*)(C16 + (size_t)(row + 8) * 256 + col) = __floats2half2_rn(ox1, oy1);
        }
    }
}

// ---------------- pooling + heads ----------------
__device__ __forceinline__ int lower_bound_i(const int* __restrict__ a, int n, int key) {
    int lo = 0, hi = n;
    while (lo < hi) {
        int mid = (lo + hi) >> 1;
        if (a[mid] < key) lo = mid + 1; else hi = mid;
    }
    return lo;
}
__global__ __launch_bounds__(256)
void pool_heads_kernel(const __half* __restrict__ h, const int* __restrict__ batch,
                       const float* __restrict__ Wmu, const float* __restrict__ bmu,
                       const float* __restrict__ Wlv, const float* __restrict__ blv,
                       float* __restrict__ out, int n, int g_total) {
    int g = blockIdx.x;
    __shared__ float hg[256];
    int lo = lower_bound_i(batch, n, g);
    int hi = lower_bound_i(batch, n, g + 1);
    int tid = threadIdx.x;
    float s = 0.f;
    for (int i = lo; i < hi; i++) s += __half2float(h[(size_t)i * 256 + tid]);
    float cnt = (float)(hi - lo);
    hg[tid] = s / fmaxf(cnt, 1.0f);
    __syncthreads();
    if (tid < 64) {
        float m = bmu[tid];
        #pragma unroll 8
        for (int k = 0; k < 256; k++) m = fmaf(hg[k], Wmu[k * 64 + tid], m);
        out[g * 64 + tid] = m;
    } else if (tid < 128) {
        int t = tid - 64;
        float m = blv[t];
        #pragma unroll 8
        for (int k = 0; k < 256; k++) m = fmaf(hg[k], Wlv[k * 64 + t], m);
        out[(size_t)g_total * 64 + g * 64 + t] = m;
    }
}

// ---------------- launch ----------------
extern "C" void kernel_launch(void* const* d_in, const int* in_sizes, int n_in,
                              void* d_out, int out_size) {
    const float* x     = (const float*)d_in[0];
    const int*   ei    = (const int*)d_in[1];
    const int*   batch = (const int*)d_in[2];
    int wi = (n_in >= 12) ? 4 : 3;
    const float* W1  = (const float*)d_in[wi + 0];
    const float* b1  = (const float*)d_in[wi + 1];
    const float* W2  = (const float*)d_in[wi + 2];
    const float* b2  = (const float*)d_in[wi + 3];
    const float* Wmu = (const float*)d_in[wi + 4];
    const float* bmu = (const float*)d_in[wi + 5];
    const float* Wlv = (const float*)d_in[wi + 6];
    const float* blv = (const float*)d_in[wi + 7];
    float* out = (float*)d_out;

    int n = in_sizes[0] / 128;
    int e = in_sizes[1] / 2;
    int g = out_size / 128;

    static __half* p_x16 = nullptr;
    static __half* p_a16 = nullptr;
    static __half* p_h16 = nullptr;
    static __half* p_w1h = nullptr; static __half* p_w1l = nullptr;
    static __half* p_w2h = nullptr; static __half* p_w2l = nullptr;
    if (!p_x16) {
        cudaGetSymbolAddress((void**)&p_x16, g_x16);
        cudaGetSymbolAddress((void**)&p_a16, g_a16);
        cudaGetSymbolAddress((void**)&p_h16, g_h16);
        cudaGetSymbolAddress((void**)&p_w1h, g_W1h);
        cudaGetSymbolAddress((void**)&p_w1l, g_W1l);
        cudaGetSymbolAddress((void**)&p_w2h, g_W2h);
        cudaGetSymbolAddress((void**)&p_w2l, g_W2l);
        cudaFuncSetAttribute(gemm_f16<128>, cudaFuncAttributeMaxDynamicSharedMemorySize, GEMM_SMEM);
        cudaFuncSetAttribute(gemm_f16<256>, cudaFuncAttributeMaxDynamicSharedMemorySize, GEMM_SMEM);
    }

    int nb = (n + 1023) / 1024;
    int setup_elems = n * 32;
    if (setup_elems < 256 * 256) setup_elems = 256 * 256;

    setup_kernel<<<(setup_elems + 255) / 256, 256>>>(x, W1, W2, p_w1h, p_w1l, p_w2h, p_w2l, p_x16, n);
    if ((e & 3) == 0) hist4_kernel<<<(e / 4 + 255) / 256, 256>>>(ei, e);
    else              hist1_kernel<<<(e + 255) / 256, 256>>>(ei, e);
    scan1_kernel<<<nb, 1024>>>(n);
    scan3_kernel<<<(n + 255) / 256, 256>>>(n, e);
    if ((e & 3) == 0) fill4_kernel<<<(e / 4 + 255) / 256, 256>>>(ei, e);
    else              fill1_kernel<<<(e + 255) / 256, 256>>>(ei, e);

    agg_f16_kernel<128><<<(n + 7) / 8, 256>>>(p_x16, p_a16, n);
    gemm_f16<128><<<dim3((n + 127) / 128, 2), 256, GEMM_SMEM>>>(p_a16, p_w1h, p_w1l, b1, p_h16, n);
    agg_f16_kernel<256><<<(n + 7) / 8, 256>>>(p_h16, p_a16, n);
    gemm_f16<256><<<dim3((n + 127) / 128, 2), 256, GEMM_SMEM>>>(p_a16, p_w2h, p_w2l, b2, p_h16, n);
    pool_heads_kernel<<<g, 256>>>(p_h16, batch, Wmu, bmu, Wlv, blv, out, n, g);
}

// round 10
// speedup vs baseline: 1.9533x; 1.0432x over previous
#include <cuda_runtime.h>
#include <cuda_bf16.h>
#include <cuda_fp16.h>
#include <stdint.h>

#define MAX_N 50000
#define MAX_E 800000
#define HD    256

// ---------------- scratch ----------------
__device__ int   g_deg[MAX_N];
__device__ int   g_rowptr[MAX_N + 1];
__device__ int   g_cursor[MAX_N];
__device__ int   g_esrc[MAX_E];
__device__ float g_dinv[MAX_N];
__device__ int   g_bsum[64];
__device__ int   g_flag[64];
__device__ __align__(16) __half g_x16[(size_t)MAX_N * 128];
__device__ __align__(16) __half g_a16[(size_t)MAX_N * 256];
__device__ __align__(16) __half g_h16[(size_t)MAX_N * 256];
// fp16 weights, transposed [n][k]; Wl pre-scaled by 512 (subnormal-safe)
__device__ __half g_W1h[256 * 128];
__device__ __half g_W1l[256 * 128];
__device__ __half g_W2h[256 * 256];
__device__ __half g_W2l[256 * 256];

// ---------------- fused setup: zero deg/flags + weight split + x->fp16 -----
__global__ void setup_kernel(const float* __restrict__ x,
                             const float* __restrict__ W1, const float* __restrict__ W2,
                             __half* __restrict__ W1h, __half* __restrict__ W1l,
                             __half* __restrict__ W2h, __half* __restrict__ W2l,
                             __half* __restrict__ x16, int n) {
    int i = blockIdx.x * blockDim.x + threadIdx.x;
    if (i < n) g_deg[i] = 0;
    if (i < 64) g_flag[i] = 0;
    if (i < 256 * 128) {
        int nn = i >> 7, k = i & 127;
        float w = W1[k * 256 + nn];
        __half h = __float2half_rn(w);
        W1h[i] = h;
        W1l[i] = __float2half_rn((w - __half2float(h)) * 512.0f);
    }
    if (i < 256 * 256) {
        int nn = i >> 8, k = i & 255;
        float w = W2[k * 256 + nn];
        __half h = __float2half_rn(w);
        W2h[i] = h;
        W2l[i] = __float2half_rn((w - __half2float(h)) * 512.0f);
    }
    if (i < n * 32) {
        float4 v = ((const float4*)x)[i];
        uint2 o;
        __half2 p0 = __floats2half2_rn(v.x, v.y);
        __half2 p1 = __floats2half2_rn(v.z, v.w);
        o.x = *(uint32_t*)&p0;
        o.y = *(uint32_t*)&p1;
        ((uint2*)x16)[i] = o;
    }
}

// MLP=8 histogram over dst
__global__ void hist8_kernel(const int* __restrict__ ei, int e) {
    int i = (blockIdx.x * blockDim.x + threadIdx.x) * 8;
    if (i + 7 < e) {
        int4 d0 = *(const int4*)(ei + e + i);
        int4 d1 = *(const int4*)(ei + e + i + 4);
        atomicAdd(&g_deg[d0.x], 1); atomicAdd(&g_deg[d0.y], 1);
        atomicAdd(&g_deg[d0.z], 1); atomicAdd(&g_deg[d0.w], 1);
        atomicAdd(&g_deg[d1.x], 1); atomicAdd(&g_deg[d1.y], 1);
        atomicAdd(&g_deg[d1.z], 1); atomicAdd(&g_deg[d1.w], 1);
    } else {
        for (int j = i; j < e; j++) atomicAdd(&g_deg[ei[e + j]], 1);
    }
}
__global__ void hist1_kernel(const int* __restrict__ ei, int e) {
    int i = blockIdx.x * blockDim.x + threadIdx.x;
    if (i < e) atomicAdd(&g_deg[ei[e + i]], 1);
}

// single-pass scan with aggregate lookback (<=64 blocks, all co-resident)
__global__ __launch_bounds__(1024)
void scan_kernel(int n, int e) {
    int tid = threadIdx.x, bid = blockIdx.x;
    int lane = tid & 31, wrp = tid >> 5;
    int i = bid * 1024 + tid;
    int v = (i < n) ? g_deg[i] : 0;
    if (i < n) g_dinv[i] = rsqrtf((float)(v + 1));
    // warp inclusive scan
    int s = v;
    #pragma unroll
    for (int d = 1; d < 32; d <<= 1) {
        int t = __shfl_up_sync(0xffffffffu, s, d);
        if (lane >= d) s += t;
    }
    __shared__ int wsum[32];
    if (lane == 31) wsum[wrp] = s;
    __syncthreads();
    if (wrp == 0) {
        int ws = wsum[lane];
        #pragma unroll
        for (int d = 1; d < 32; d <<= 1) {
            int t = __shfl_up_sync(0xffffffffu, ws, d);
            if (lane >= d) ws += t;
        }
        wsum[lane] = ws;
    }
    __syncthreads();
    int incl = s + (wrp ? wsum[wrp - 1] : 0);
    int total = wsum[31];
    if (tid == 0) {
        g_bsum[bid] = total;
        __threadfence();
        ((volatile int*)g_flag)[bid] = 1;
    }
    __shared__ int s_off;
    if (tid == 0) s_off = 0;
    __syncthreads();
    if (tid < bid) {
        while (((volatile int*)g_flag)[tid] == 0) {}
        __threadfence();
        atomicAdd(&s_off, ((volatile int*)g_bsum)[tid]);
    }
    __syncthreads();
    int off = s_off;
    if (i < n) {
        int r = off + incl - v;
        g_rowptr[i] = r;
        g_cursor[i] = r;
    }
    if (i == 0) g_rowptr[n] = e;
}

// MLP=8 CSR bucket fill
__global__ void fill8_kernel(const int* __restrict__ ei, int e) {
    int i = (blockIdx.x * blockDim.x + threadIdx.x) * 8;
    if (i + 7 < e) {
        int4 s0 = *(const int4*)(ei + i);
        int4 s1 = *(const int4*)(ei + i + 4);
        int4 d0 = *(const int4*)(ei + e + i);
        int4 d1 = *(const int4*)(ei + e + i + 4);
        int p0 = atomicAdd(&g_cursor[d0.x], 1);
        int p1 = atomicAdd(&g_cursor[d0.y], 1);
        int p2 = atomicAdd(&g_cursor[d0.z], 1);
        int p3 = atomicAdd(&g_cursor[d0.w], 1);
        int p4 = atomicAdd(&g_cursor[d1.x], 1);
        int p5 = atomicAdd(&g_cursor[d1.y], 1);
        int p6 = atomicAdd(&g_cursor[d1.z], 1);
        int p7 = atomicAdd(&g_cursor[d1.w], 1);
        g_esrc[p0] = s0.x; g_esrc[p1] = s0.y; g_esrc[p2] = s0.z; g_esrc[p3] = s0.w;
        g_esrc[p4] = s1.x; g_esrc[p5] = s1.y; g_esrc[p6] = s1.z; g_esrc[p7] = s1.w;
    } else {
        for (int j = i; j < e; j++) {
            int src = ei[j];
            int pos = atomicAdd(&g_cursor[ei[e + j]], 1);
            g_esrc[pos] = src;
        }
    }
}
__global__ void fill1_kernel(const int* __restrict__ ei, int e) {
    int i = blockIdx.x * blockDim.x + threadIdx.x;
    if (i < e) {
        int src = ei[i];
        int pos = atomicAdd(&g_cursor[ei[e + i]], 1);
        g_esrc[pos] = src;
    }
}

// ---------------- fp16 aggregation ----------------
template <int F>
__global__ void agg_f16_kernel(const __half* __restrict__ xh, __half* __restrict__ out, int n) {
    int warp = blockIdx.x * (blockDim.x >> 5) + (threadIdx.x >> 5);
    int lane = threadIdx.x & 31;
    if (warp >= n) return;
    constexpr int VH = F / 32;
    constexpr int V2 = VH / 2;
    float di = g_dinv[warp];
    float acc[VH];
    const uint32_t* __restrict__ xw = (const uint32_t*)xh;
    {
        #pragma unroll
        for (int v = 0; v < V2; v++) {
            uint32_t u = xw[(size_t)warp * (F / 2) + lane * V2 + v];
            float2 t = __half22float2(*(__half2*)&u);
            acc[2 * v] = di * t.x;
            acc[2 * v + 1] = di * t.y;
        }
    }
    int beg = g_rowptr[warp], end = g_rowptr[warp + 1];
    int e = beg;
    for (; e + 1 < end; e += 2) {
        int s0 = g_esrc[e], s1 = g_esrc[e + 1];
        float w0 = g_dinv[s0], w1 = g_dinv[s1];
        uint32_t u0[V2], u1[V2];
        if constexpr (V2 == 4) {
            uint4 a = *(const uint4*)(xw + (size_t)s0 * (F / 2) + lane * 4);
            uint4 b = *(const uint4*)(xw + (size_t)s1 * (F / 2) + lane * 4);
            u0[0] = a.x; u0[1] = a.y; u0[2] = a.z; u0[3] = a.w;
            u1[0] = b.x; u1[1] = b.y; u1[2] = b.z; u1[3] = b.w;
        } else {
            uint2 a = *(const uint2*)(xw + (size_t)s0 * (F / 2) + lane * 2);
            uint2 b = *(const uint2*)(xw + (size_t)s1 * (F / 2) + lane * 2);
            u0[0] = a.x; u0[1] = a.y;
            u1[0] = b.x; u1[1] = b.y;
        }
        #pragma unroll
        for (int v = 0; v < V2; v++) {
            float2 t0 = __half22float2(*(__half2*)&u0[v]);
            float2 t1 = __half22float2(*(__half2*)&u1[v]);
            acc[2 * v]     = fmaf(w0, t0.x, acc[2 * v]);
            acc[2 * v + 1] = fmaf(w0, t0.y, acc[2 * v + 1]);
            acc[2 * v]     = fmaf(w1, t1.x, acc[2 * v]);
            acc[2 * v + 1] = fmaf(w1, t1.y, acc[2 * v + 1]);
        }
    }
    if (e < end) {
        int s = g_esrc[e];
        float w = g_dinv[s];
        #pragma unroll
        for (int v = 0; v < V2; v++) {
            uint32_t u = xw[(size_t)s * (F / 2) + lane * V2 + v];
            float2 t = __half22float2(*(__half2*)&u);
            acc[2 * v]     = fmaf(w, t.x, acc[2 * v]);
            acc[2 * v + 1] = fmaf(w, t.y, acc[2 * v + 1]);
        }
    }
    __half2* op = (__half2*)(out + (size_t)warp * F + lane * VH);
    #pragma unroll
    for (int v = 0; v < V2; v++)
        op[v] = __floats2half2_rn(di * acc[2 * v], di * acc[2 * v + 1]);
}

// ---------------- fp16 tensor GEMM: ldmatrix + cp.async, KC=64 ------------
__device__ __forceinline__ void mma_f16(float* c, const uint32_t* a, uint32_t b0, uint32_t b1) {
    asm volatile(
        "mma.sync.aligned.m16n8k16.row.col.f32.f16.f16.f32 "
        "{%0,%1,%2,%3}, {%4,%5,%6,%7}, {%8,%9}, {%0,%1,%2,%3};"
        : "+f"(c[0]), "+f"(c[1]), "+f"(c[2]), "+f"(c[3])
        : "r"(a[0]), "r"(a[1]), "r"(a[2]), "r"(a[3]), "r"(b0), "r"(b1));
}
__device__ __forceinline__ void ldsm4(uint32_t* r, uint32_t addr) {
    asm volatile("ldmatrix.sync.aligned.m8n8.x4.shared.b16 {%0,%1,%2,%3}, [%4];"
                 : "=r"(r[0]), "=r"(r[1]), "=r"(r[2]), "=r"(r[3]) : "r"(addr));
}
__device__ __forceinline__ void cp16(uint32_t dst, const void* src) {
    asm volatile("cp.async.cg.shared.global [%0], [%1], 16;" :: "r"(dst), "l"(src));
}
__device__ __forceinline__ uint32_t smem_u32(const void* p) {
    uint32_t a;
    asm("{.reg .u64 t; cvta.to.shared.u64 t, %1; cvt.u32.u64 %0, t;}" : "=r"(a) : "l"(p));
    return a;
}

#define KC 64
#define ROWB 144                   // 64 halves (128B) + 16B pad: ldmatrix conflict-free
#define ARRB (128 * ROWB)          // 18432 B per array
#define BUFB (3 * ARRB)            // 55296 B per buffer
#define GEMM_SMEM (2 * BUFB)       // 110592 B (occ 2 -> 216KB/SM, fits 228KB)

template <int K>
__global__ __launch_bounds__(256, 2)
void gemm_f16(const __half* __restrict__ A, const __half* __restrict__ Wh,
              const __half* __restrict__ Wl, const float* __restrict__ bias,
              __half* __restrict__ C16, int M) {
    extern __shared__ __half smem[];
    const uint32_t sbase = smem_u32(smem);
    const int tid = threadIdx.x;
    const int wid = tid >> 5;
    const int lane = tid & 31;
    const int row0 = blockIdx.x * 128;
    const int colbase = blockIdx.y * 128;
    const int m_off = (wid & 3) * 32;
    const int n_off = (wid >> 2) * 64;
    const __half2 inv512 = __half2half2(__float2half(0.001953125f));
    constexpr int CHUNKS = K / KC;

    float acc[2][8][4];
    #pragma unroll
    for (int mt = 0; mt < 2; mt++)
        #pragma unroll
        for (int nt = 0; nt < 8; nt++)
            #pragma unroll
            for (int q = 0; q < 4; q++) acc[mt][nt][q] = 0.f;

    auto stage = [&](int c, int b) {
        int k0 = c * KC;
        uint32_t buf = sbase + b * BUFB;
        #pragma unroll
        for (int it = 0; it < 4; it++) {
            int i = tid + it * 256;     // 0..1023
            int r = i >> 3;             // 0..127
            int q = (i & 7) * 8;        // halves 0..56
            int rr = row0 + r; if (rr >= M) rr = M - 1;
            cp16(buf + r * ROWB + q * 2, A + (size_t)rr * K + k0 + q);
            int nn = colbase + r;
            cp16(buf + ARRB + r * ROWB + q * 2, Wh + (size_t)nn * K + k0 + q);
            cp16(buf + 2 * ARRB + r * ROWB + q * 2, Wl + (size_t)nn * K + k0 + q);
        }
        asm volatile("cp.async.commit_group;");
    };

    const int a_rsel = lane & 15;
    const int a_ksel = (lane >> 4) * 8;
    const int b_nsel = (lane & 7) + ((lane >> 4) << 3);
    const int b_koff = ((lane >> 3) & 1) * 8;

    auto compute = [&](int b) {
        uint32_t sa = sbase + b * BUFB;
        uint32_t sbh = sa + ARRB;
        uint32_t sbl = sa + 2 * ARRB;
        #pragma unroll
        for (int ks = 0; ks < KC; ks += 16) {
            uint32_t ah[2][4], as[2][4];
            #pragma unroll
            for (int mt = 0; mt < 2; mt++) {
                uint32_t addr = sa + (m_off + mt * 16 + a_rsel) * ROWB + (ks + a_ksel) * 2;
                ldsm4(ah[mt], addr);
                #pragma unroll
                for (int q = 0; q < 4; q++) {
                    __half2 h = __hmul2(*(__half2*)&ah[mt][q], inv512);
                    as[mt][q] = *(uint32_t*)&h;
                }
            }
            #pragma unroll
            for (int p = 0; p < 4; p++) {
                uint32_t off = (n_off + p * 16 + b_nsel) * ROWB + (ks + b_koff) * 2;
                uint32_t bh4[4], bl4[4];
                ldsm4(bh4, sbh + off);
                ldsm4(bl4, sbl + off);
                // all bh-term MMAs first, then bl-term: acc reuse distance 4
                #pragma unroll
                for (int mt = 0; mt < 2; mt++) {
                    mma_f16(acc[mt][2 * p],     ah[mt], bh4[0], bh4[1]);
                    mma_f16(acc[mt][2 * p + 1], ah[mt], bh4[2], bh4[3]);
                }
                #pragma unroll
                for (int mt = 0; mt < 2; mt++) {
                    mma_f16(acc[mt][2 * p],     as[mt], bl4[0], bl4[1]);
                    mma_f16(acc[mt][2 * p + 1], as[mt], bl4[2], bl4[3]);
                }
            }
        }
    };

    stage(0, 0);
    asm volatile("cp.async.wait_group 0;");
    __syncthreads();
    for (int c = 0; c < CHUNKS; c++) {
        if (c + 1 < CHUNKS) stage(c + 1, (c + 1) & 1);
        compute(c & 1);
        if (c + 1 < CHUNKS) asm volatile("cp.async.wait_group 0;");
        __syncthreads();
    }

    // epilogue: bias + relu + fp16 store
    #pragma unroll
    for (int mt = 0; mt < 2; mt++) {
        int row = row0 + m_off + mt * 16 + (lane >> 2);
        #pragma unroll
        for (int nt = 0; nt < 8; nt++) {
            int col = colbase + n_off + nt * 8 + (lane & 3) * 2;
            float b0 = bias[col], b1 = bias[col + 1];
            float ox0 = acc[mt][nt][0] + b0, oy0 = acc[mt][nt][1] + b1;
            float ox1 = acc[mt][nt][2] + b0, oy1 = acc[mt][nt][3] + b1;
            ox0 = ox0 > 0.f ? ox0 : 0.f; oy0 = oy0 > 0.f ? oy0 : 0.f;
            ox1 = ox1 > 0.f ? ox1 : 0.f; oy1 = oy1 > 0.f ? oy1 : 0.f;
            if (row < M)
                *(__half2*)(C16 + (size_t)row * 256 + col) = __floats2half2_rn(ox0, oy0);
            if (row + 8 < M)
                *(__half2*)(C16 + (size_t)(row + 8) * 256 + col) = __floats2half2_rn(ox1, oy1);
        }
    }
}

// ---------------- pooling + heads ----------------
__device__ __forceinline__ int lower_bound_i(const int* __restrict__ a, int n, int key) {
    int lo = 0, hi = n;
    while (lo < hi) {
        int mid = (lo + hi) >> 1;
        if (a[mid] < key) lo = mid + 1; else hi = mid;
    }
    return lo;
}
__global__ __launch_bounds__(256)
void pool_heads_kernel(const __half* __restrict__ h, const int* __restrict__ batch,
                       const float* __restrict__ Wmu, const float* __restrict__ bmu,
                       const float* __restrict__ Wlv, const float* __restrict__ blv,
                       float* __restrict__ out, int n, int g_total) {
    int g = blockIdx.x;
    __shared__ float hg[256];
    int lo = lower_bound_i(batch, n, g);
    int hi = lower_bound_i(batch, n, g + 1);
    int tid = threadIdx.x;
    float s = 0.f;
    for (int i = lo; i < hi; i++) s += __half2float(h[(size_t)i * 256 + tid]);
    float cnt = (float)(hi - lo);
    hg[tid] = s / fmaxf(cnt, 1.0f);
    __syncthreads();
    if (tid < 64) {
        float m = bmu[tid];
        #pragma unroll 8
        for (int k = 0; k < 256; k++) m = fmaf(hg[k], Wmu[k * 64 + tid], m);
        out[g * 64 + tid] = m;
    } else if (tid < 128) {
        int t = tid - 64;
        float m = blv[t];
        #pragma unroll 8
        for (int k = 0; k < 256; k++) m = fmaf(hg[k], Wlv[k * 64 + t], m);
        out[(size_t)g_total * 64 + g * 64 + t] = m;
    }
}

// ---------------- launch ----------------
extern "C" void kernel_launch(void* const* d_in, const int* in_sizes, int n_in,
                              void* d_out, int out_size) {
    const float* x     = (const float*)d_in[0];
    const int*   ei    = (const int*)d_in[1];
    const int*   batch = (const int*)d_in[2];
    int wi = (n_in >= 12) ? 4 : 3;
    const float* W1  = (const float*)d_in[wi + 0];
    const float* b1  = (const float*)d_in[wi + 1];
    const float* W2  = (const float*)d_in[wi + 2];
    const float* b2  = (const float*)d_in[wi + 3];
    const float* Wmu = (const float*)d_in[wi + 4];
    const float* bmu = (const float*)d_in[wi + 5];
    const float* Wlv = (const float*)d_in[wi + 6];
    const float* blv = (const float*)d_in[wi + 7];
    float* out = (float*)d_out;

    int n = in_sizes[0] / 128;
    int e = in_sizes[1] / 2;
    int g = out_size / 128;

    static __half* p_x16 = nullptr;
    static __half* p_a16 = nullptr;
    static __half* p_h16 = nullptr;
    static __half* p_w1h = nullptr; static __half* p_w1l = nullptr;
    static __half* p_w2h = nullptr; static __half* p_w2l = nullptr;
    if (!p_x16) {
        cudaGetSymbolAddress((void**)&p_x16, g_x16);
        cudaGetSymbolAddress((void**)&p_a16, g_a16);
        cudaGetSymbolAddress((void**)&p_h16, g_h16);
        cudaGetSymbolAddress((void**)&p_w1h, g_W1h);
        cudaGetSymbolAddress((void**)&p_w1l, g_W1l);
        cudaGetSymbolAddress((void**)&p_w2h, g_W2h);
        cudaGetSymbolAddress((void**)&p_w2l, g_W2l);
        cudaFuncSetAttribute(gemm_f16<128>, cudaFuncAttributeMaxDynamicSharedMemorySize, GEMM_SMEM);
        cudaFuncSetAttribute(gemm_f16<256>, cudaFuncAttributeMaxDynamicSharedMemorySize, GEMM_SMEM);
    }

    int nb = (n + 1023) / 1024;
    int setup_elems = n * 32;
    if (setup_elems < 256 * 256) setup_elems = 256 * 256;

    setup_kernel<<<(setup_elems + 255) / 256, 256>>>(x, W1, W2, p_w1h, p_w1l, p_w2h, p_w2l, p_x16, n);
    if ((e & 7) == 0) hist8_kernel<<<(e / 8 + 255) / 256, 256>>>(ei, e);
    else              hist1_kernel<<<(e + 255) / 256, 256>>>(ei, e);
    scan_kernel<<<nb, 1024>>>(n, e);
    if ((e & 7) == 0) fill8_kernel<<<(e / 8 + 255) / 256, 256>>>(ei, e);
    else              fill1_kernel<<<(e + 255) / 256, 256>>>(ei, e);

    agg_f16_kernel<128><<<(n + 7) / 8, 256>>>(p_x16, p_a16, n);
    gemm_f16<128><<<dim3((n + 127) / 128, 2), 256, GEMM_SMEM>>>(p_a16, p_w1h, p_w1l, b1, p_h16, n);
    agg_f16_kernel<256><<<(n + 7) / 8, 256>>>(p_h16, p_a16, n);
    gemm_f16<256><<<dim3((n + 127) / 128, 2), 256, GEMM_SMEM>>>(p_a16, p_w2h, p_w2l, b2, p_h16, n);
    pool_heads_kernel<<<g, 256>>>(p_h16, batch, Wmu, bmu, Wlv, blv, out, n, g);
}